// round 2
// baseline (speedup 1.0000x reference)
#include <cuda_runtime.h>
#include <float.h>

#define NB 2
#define NN 512
#define NH 8
#define CH 128      // n_head * head_hidden
#define EH 64       // edge hidden
#define QKVW 384
#define TJ 64       // j-rows per block in edge kernel

// Scratch (device globals; no allocation allowed)
__device__ float g_QKV[NB * NN * QKVW];              // q|k|v per node row
__device__ float g_LOG[(size_t)NB * NN * NN * NH];   // attention logits

// ---------------------------------------------------------------------------
// Kernel A: qkv = x @ Wqkv + bqkv.   1024 blocks x 384 threads.
// ---------------------------------------------------------------------------
__global__ void __launch_bounds__(QKVW) qkv_kernel(
    const float* __restrict__ x,
    const float* __restrict__ W,
    const float* __restrict__ bias)
{
    __shared__ float xs[CH];
    int row = blockIdx.x;      // b*512 + i
    int col = threadIdx.x;     // 0..383
    if (col < CH) xs[col] = x[row * CH + col];
    __syncthreads();
    float acc = bias[col];
#pragma unroll 16
    for (int k = 0; k < CH; k++) acc = fmaf(xs[k], W[k * QKVW + col], acc);
    g_QKV[row * QKVW + col] = acc;
}

// ---------------------------------------------------------------------------
// Kernel B: fused per (b,i, j-tile):
//   e   = edge_attr @ We + be                (TJ x 128)
//   raw = q_i * k_j * e                      (kept in regs)
//   logits[b,i,j,h] = sum_d raw / 4          -> g_LOG
//   edge_out = raw @ Weo + beo               (TJ x 64)
// 256 threads. Thread t: j0=(t>>4)*4 (4 j rows), c0=(t&15)*8 (8 channels).
// ---------------------------------------------------------------------------
__global__ void __launch_bounds__(256) edge_kernel(
    const float* __restrict__ edge_attr,
    const float* __restrict__ We,  const float* __restrict__ be,
    const float* __restrict__ Weo, const float* __restrict__ beo,
    float* __restrict__ edge_out)
{
    extern __shared__ float sm[];
    float* A  = sm;                 // TJ*132 floats
    float* B  = sm + TJ * 132;      // 8192 floats
    float* qs = B + CH * EH;        // 128 floats

    const int t     = threadIdx.x;
    const int jt    = blockIdx.x;        // 0..7
    const int bi    = blockIdx.y;        // 0..1023
    const int b     = bi >> 9;
    const int jbase = jt * TJ;

    // --- cooperative loads: edge tile (stride 68), We, q row ---
    const float4* ef4 = (const float4*)(edge_attr + ((size_t)bi * NN + jbase) * EH);
    float4* Af4 = (float4*)A;
    float4* Bf4 = (float4*)B;
#pragma unroll
    for (int s = 0; s < 4; s++) {
        int fi = t + s * 256;            // 1024 float4s total
        int j = fi >> 4, k4 = fi & 15;
        Af4[j * 17 + k4] = ef4[fi];      // row stride 68 floats = 17 float4
    }
    const float4* wef4 = (const float4*)We;
#pragma unroll
    for (int s = 0; s < 8; s++) Bf4[t + s * 256] = wef4[t + s * 256];
    if (t < CH) qs[t] = g_QKV[bi * QKVW + t];
    __syncthreads();

    const int j0 = (t >> 4) * 4;
    const int c0 = (t & 15) * 8;

    // --- phase 1: e-GEMM (k over 64), 4j x 8c register tile ---
    float acc[4][8];
#pragma unroll
    for (int jj = 0; jj < 4; jj++)
#pragma unroll
        for (int cc = 0; cc < 8; cc++) acc[jj][cc] = 0.f;

#pragma unroll 2
    for (int k = 0; k < EH; k++) {
        float4 w0 = Bf4[k * 32 + (c0 >> 2)];
        float4 w1 = Bf4[k * 32 + (c0 >> 2) + 1];
        float wv[8] = {w0.x, w0.y, w0.z, w0.w, w1.x, w1.y, w1.z, w1.w};
        float ev[4];
#pragma unroll
        for (int jj = 0; jj < 4; jj++) ev[jj] = A[(j0 + jj) * 68 + k];
#pragma unroll
        for (int jj = 0; jj < 4; jj++)
#pragma unroll
            for (int cc = 0; cc < 8; cc++)
                acc[jj][cc] = fmaf(ev[jj], wv[cc], acc[jj][cc]);
    }

    // --- raw = (e + be) * q * k ;  per-head logit partials ---
    float4 ba = __ldg((const float4*)(be + c0));
    float4 bb = __ldg((const float4*)(be + c0 + 4));
    float bev[8] = {ba.x, ba.y, ba.z, ba.w, bb.x, bb.y, bb.z, bb.w};
    float4 qa = *(const float4*)(qs + c0);
    float4 qb = *(const float4*)(qs + c0 + 4);
    float qv[8] = {qa.x, qa.y, qa.z, qa.w, qb.x, qb.y, qb.z, qb.w};

    float lg[4];
#pragma unroll
    for (int jj = 0; jj < 4; jj++) {
        int jg = jbase + j0 + jj;
        const float4* Kp = (const float4*)(g_QKV + ((b * NN + jg) * QKVW + CH + c0));
        float4 k0 = __ldg(Kp);
        float4 k1 = __ldg(Kp + 1);
        float kv[8] = {k0.x, k0.y, k0.z, k0.w, k1.x, k1.y, k1.z, k1.w};
        float p = 0.f;
#pragma unroll
        for (int cc = 0; cc < 8; cc++) {
            float r = (acc[jj][cc] + bev[cc]) * qv[cc] * kv[cc];
            acc[jj][cc] = r;
            p += r;
        }
        lg[jj] = p;
    }
    // pair (t, t^1) covers the 16 d's of one head
#pragma unroll
    for (int jj = 0; jj < 4; jj++)
        lg[jj] += __shfl_xor_sync(0xffffffffu, lg[jj], 1);
    if ((t & 1) == 0) {
        int h = (t & 15) >> 1;
#pragma unroll
        for (int jj = 0; jj < 4; jj++)
            g_LOG[((size_t)bi * NN + jbase + j0 + jj) * NH + h] = lg[jj] * 0.25f;
    }

    __syncthreads();   // everyone done reading A(edge)/B(We)

    // --- write raw tile (stride 132), load Weo ---
#pragma unroll
    for (int jj = 0; jj < 4; jj++) {
        float4* dst = (float4*)(A + (j0 + jj) * 132 + c0);
        dst[0] = make_float4(acc[jj][0], acc[jj][1], acc[jj][2], acc[jj][3]);
        dst[1] = make_float4(acc[jj][4], acc[jj][5], acc[jj][6], acc[jj][7]);
    }
    const float4* weof4 = (const float4*)Weo;
#pragma unroll
    for (int s = 0; s < 8; s++) Bf4[t + s * 256] = weof4[t + s * 256];
    __syncthreads();

    // --- phase 2: edge_out = raw @ Weo + beo, 4j x 4eo tile ---
    const int eo0 = (t & 15) * 4;
    float o[4][4];
#pragma unroll
    for (int jj = 0; jj < 4; jj++)
#pragma unroll
        for (int ee = 0; ee < 4; ee++) o[jj][ee] = 0.f;

#pragma unroll 2
    for (int c = 0; c < CH; c++) {
        float4 w = Bf4[c * 16 + (eo0 >> 2)];
        float wv[4] = {w.x, w.y, w.z, w.w};
        float rv[4];
#pragma unroll
        for (int jj = 0; jj < 4; jj++) rv[jj] = A[(j0 + jj) * 132 + c];
#pragma unroll
        for (int jj = 0; jj < 4; jj++)
#pragma unroll
            for (int ee = 0; ee < 4; ee++)
                o[jj][ee] = fmaf(rv[jj], wv[ee], o[jj][ee]);
    }
    float4 bo = __ldg((const float4*)(beo + eo0));
#pragma unroll
    for (int jj = 0; jj < 4; jj++) {
        float4 val = make_float4(o[jj][0] + bo.x, o[jj][1] + bo.y,
                                 o[jj][2] + bo.z, o[jj][3] + bo.w);
        *(float4*)(edge_out + (((size_t)bi * NN + jbase + j0 + jj) * EH + eo0)) = val;
    }
}

// ---------------------------------------------------------------------------
// Kernel C: masked softmax over j (per b,i,h), node = att @ v, then
// node_out = node @ Wno + bno.   1024 blocks x 128 threads (thread = channel).
// mask arrives as int32 (JAX bool -> int32 in the harness).
// ---------------------------------------------------------------------------
__global__ void __launch_bounds__(CH) softmax_node_kernel(
    const int* __restrict__ mask,
    const float* __restrict__ Wno, const float* __restrict__ bno,
    float* __restrict__ node_out)
{
    __shared__ float ls[NN * NH];     // 16 KB logits (masked, then exp'd)
    __shared__ float node_s[CH];
    __shared__ int msk[NN];

    int bi = blockIdx.x;
    int b  = bi >> 9;
    int t  = threadIdx.x;             // channel c = h*16 + d

    for (int j = t; j < NN; j += CH) msk[j] = mask[b * NN + j];
    __syncthreads();

    const float4* Lp = (const float4*)(g_LOG + (size_t)bi * NN * NH);
    float4* lsf4 = (float4*)ls;
    for (int fi = t; fi < NN * NH / 4; fi += CH) {
        float4 v = Lp[fi];
        if (!msk[fi >> 1]) { v.x = v.y = v.z = v.w = -FLT_MAX; }
        lsf4[fi] = v;
    }
    __syncthreads();

    int h = t >> 4;
    float m = -FLT_MAX;
    for (int j = 0; j < NN; j++) m = fmaxf(m, ls[j * NH + h]);
    // exponentiate in place (threads with same h write identical values)
    float ssum = 0.f;
    for (int j = 0; j < NN; j++) {
        float p = __expf(ls[j * NH + h] - m);
        ls[j * NH + h] = p;
        ssum += p;
    }
    float inv = 1.f / ssum;
    __syncthreads();

    float acc = 0.f;
    const float* Vp = g_QKV + (b * NN) * QKVW + 2 * CH + t;
    for (int j = 0; j < NN; j++)
        acc = fmaf(ls[j * NH + h], Vp[j * QKVW], acc);
    node_s[t] = acc * inv;
    __syncthreads();

    float o = bno[t];
#pragma unroll 8
    for (int k = 0; k < CH; k++) o = fmaf(node_s[k], Wno[k * CH + t], o);
    node_out[bi * CH + t] = o;
}

// ---------------------------------------------------------------------------
extern "C" void kernel_launch(void* const* d_in, const int* in_sizes, int n_in,
                              void* d_out, int out_size)
{
    const float* x         = (const float*)d_in[0];
    const float* edge_attr = (const float*)d_in[1];
    const int*   mask      = (const int*)d_in[2];
    const float* Wqkv      = (const float*)d_in[3];
    const float* bqkv      = (const float*)d_in[4];
    const float* We        = (const float*)d_in[5];
    const float* be        = (const float*)d_in[6];
    const float* Wno       = (const float*)d_in[7];
    const float* bno       = (const float*)d_in[8];
    const float* Weo       = (const float*)d_in[9];
    const float* beo       = (const float*)d_in[10];

    float* out      = (float*)d_out;
    float* node_out = out;                       // (2,512,128)
    float* edge_out = out + NB * NN * CH;        // (2,512,512,64)

    qkv_kernel<<<NB * NN, QKVW>>>(x, Wqkv, bqkv);

    size_t shmem = (TJ * 132 + CH * EH + CH) * sizeof(float);  // 67072 B
    cudaFuncSetAttribute(edge_kernel,
                         cudaFuncAttributeMaxDynamicSharedMemorySize,
                         (int)shmem);
    edge_kernel<<<dim3(NN / TJ, NB * NN), 256, shmem>>>(
        edge_attr, We, be, Weo, beo, edge_out);

    softmax_node_kernel<<<NB * NN, CH>>>(mask, Wno, bno, node_out);
}

// round 4
// speedup vs baseline: 1.2665x; 1.2665x over previous
#include <cuda_runtime.h>
#include <cuda_bf16.h>
#include <cstdint>
#include <float.h>

#define NB 2
#define NN 512
#define NH 8
#define CH 128      // n_head * head_hidden
#define EH 64       // edge hidden
#define QKVW 384
#define TJM 128     // j-rows per block (MMA M)

// Scratch (device globals; zero-initialized at module load)
__device__ float g_QKV[NB * NN * QKVW];              // q|k|v per node row
__device__ float g_LOG[(size_t)NB * NN * NN * NH];   // attention logits
// Pre-split weights, packed bf16x2 along K, padded strides (u32 elements)
__device__ uint32_t g_WeHi[32 * 136];   // We  [k2=32][c=128] pad 136
__device__ uint32_t g_WeLo[32 * 136];
__device__ uint32_t g_WeoHi[64 * 72];   // Weo [k2=64][eo=64] pad 72
__device__ uint32_t g_WeoLo[64 * 72];

// ---------------------------------------------------------------------------
// helpers
// ---------------------------------------------------------------------------
__device__ __forceinline__ void split2(float a, float b, uint32_t& hi, uint32_t& lo) {
    __nv_bfloat16 ha = __float2bfloat16_rn(a);
    __nv_bfloat16 hb = __float2bfloat16_rn(b);
    float ra = a - __bfloat162float(ha);
    float rb = b - __bfloat162float(hb);
    __nv_bfloat16 la = __float2bfloat16_rn(ra);
    __nv_bfloat16 lb = __float2bfloat16_rn(rb);
    unsigned short uha = *(unsigned short*)&ha, uhb = *(unsigned short*)&hb;
    unsigned short ula = *(unsigned short*)&la, ulb = *(unsigned short*)&lb;
    hi = ((uint32_t)uhb << 16) | uha;     // low half = even-k element
    lo = ((uint32_t)ulb << 16) | ula;
}

__device__ __forceinline__ void mma_bf16(float* c,
    uint32_t a0, uint32_t a1, uint32_t a2, uint32_t a3,
    uint32_t b0, uint32_t b1)
{
    asm volatile(
        "mma.sync.aligned.m16n8k16.row.col.f32.bf16.bf16.f32 "
        "{%0,%1,%2,%3}, {%4,%5,%6,%7}, {%8,%9}, {%0,%1,%2,%3};"
        : "+f"(c[0]), "+f"(c[1]), "+f"(c[2]), "+f"(c[3])
        : "r"(a0), "r"(a1), "r"(a2), "r"(a3), "r"(b0), "r"(b1));
}

// SMEM map (u32 units)
#define OFF_B2HI 0        // 4608
#define OFF_B2LO 4608     // 4608
#define OFF_A1HI 9216     // 4608  (128 x 36)
#define OFF_A1LO 13824    // 4608
#define OFF_B1HI 18432    // 4352  (32 x 136)
#define OFF_B1LO 22784    // 4352
#define OFF_A2HI 9216     // 8704  (128 x 68)  reuses A1/B1 region
#define OFF_A2LO 17920    // 8704
#define OFF_QS   27136    // 128 floats
#define OFF_BES  27264    // 128 floats
#define SMEM_U32 27392    // 109568 bytes

// ---------------------------------------------------------------------------
// Kernel P: pre-split weights (once per launch, trivial)
// ---------------------------------------------------------------------------
__global__ void prep_kernel(const float* __restrict__ We, const float* __restrict__ Weo) {
    int t = blockIdx.x * 256 + threadIdx.x;
    if (t < 32 * 128) {
        int k2 = t >> 7, c = t & 127;
        uint32_t h, l;
        split2(We[(2 * k2) * CH + c], We[(2 * k2 + 1) * CH + c], h, l);
        g_WeHi[k2 * 136 + c] = h; g_WeLo[k2 * 136 + c] = l;
    }
    if (t < 64 * 64) {
        int k2 = t >> 6, eo = t & 63;
        uint32_t h, l;
        split2(Weo[(2 * k2) * EH + eo], Weo[(2 * k2 + 1) * EH + eo], h, l);
        g_WeoHi[k2 * 72 + eo] = h; g_WeoLo[k2 * 72 + eo] = l;
    }
}

// ---------------------------------------------------------------------------
// Kernel A: qkv = x @ Wqkv + bqkv
// ---------------------------------------------------------------------------
__global__ void __launch_bounds__(QKVW) qkv_kernel(
    const float* __restrict__ x, const float* __restrict__ W,
    const float* __restrict__ bias)
{
    __shared__ float xs[CH];
    int row = blockIdx.x, col = threadIdx.x;
    if (col < CH) xs[col] = x[row * CH + col];
    __syncthreads();
    float acc = bias[col];
#pragma unroll 16
    for (int k = 0; k < CH; k++) acc = fmaf(xs[k], W[k * QKVW + col], acc);
    g_QKV[row * QKVW + col] = acc;
}

// ---------------------------------------------------------------------------
// Kernel B: fused edge pipeline with mma.sync bf16 3-term split.
// Grid (4, 1024), 512 threads (16 warps).
// ---------------------------------------------------------------------------
__global__ void __launch_bounds__(512) edge_mma_kernel(
    const float* __restrict__ edge_attr,
    const float* __restrict__ be, const float* __restrict__ beo,
    float* __restrict__ edge_out)
{
    extern __shared__ uint32_t smu[];
    float* qs  = (float*)(smu + OFF_QS);
    float* bes = (float*)(smu + OFF_BES);

    const int t = threadIdx.x, lane = t & 31, w = t >> 5;
    const int g = lane >> 2, c4 = lane & 3;
    const int jt = blockIdx.x, bi = blockIdx.y;
    const int b = bi >> 9, jbase = jt * TJM;

    // ---- cooperative loads ----
    {   // A1: edge tile [128 x 64] fp32 -> split bf16x2, stride 36 u32
        const float4* src = (const float4*)(edge_attr + ((size_t)bi * NN + jbase) * EH);
#pragma unroll
        for (int s = 0; s < 4; s++) {
            int fi = t + s * 512;            // 2048 float4
            int row = fi >> 4, cc4 = fi & 15;
            float4 v = src[fi];
            uint32_t h0, l0, h1, l1;
            split2(v.x, v.y, h0, l0);
            split2(v.z, v.w, h1, l1);
            int idx = row * 36 + cc4 * 2;
            smu[OFF_A1HI + idx]     = h0;
            smu[OFF_A1HI + idx + 1] = h1;
            smu[OFF_A1LO + idx]     = l0;
            smu[OFF_A1LO + idx + 1] = l1;
        }
        for (int i = t; i < 32 * 136; i += 512) {
            smu[OFF_B1HI + i] = g_WeHi[i];
            smu[OFF_B1LO + i] = g_WeLo[i];
        }
        for (int i = t; i < 64 * 72; i += 512) {
            smu[OFF_B2HI + i] = g_WeoHi[i];
            smu[OFF_B2LO + i] = g_WeoLo[i];
        }
        if (t < CH) { qs[t] = g_QKV[bi * QKVW + t]; bes[t] = be[t]; }
    }
    __syncthreads();

    // ---- phase 1: e[128,128] = A1[128,64] x We ----
    const int wm = w & 3, wn = w >> 2;
    const int m0 = wm * 32, n0 = wn * 32;

    float acc[2][4][4];
#pragma unroll
    for (int mf = 0; mf < 2; mf++)
#pragma unroll
        for (int nf = 0; nf < 4; nf++)
#pragma unroll
            for (int i = 0; i < 4; i++) acc[mf][nf][i] = 0.f;

#pragma unroll
    for (int ks = 0; ks < 4; ks++) {
        const int kb2 = ks * 8;
        uint32_t ah[2][4], al[2][4];
#pragma unroll
        for (int mf = 0; mf < 2; mf++) {
            int r0 = (m0 + mf * 16 + g) * 36 + kb2 + c4;
            int r1 = r0 + 8 * 36;
            ah[mf][0] = smu[OFF_A1HI + r0];     ah[mf][1] = smu[OFF_A1HI + r1];
            ah[mf][2] = smu[OFF_A1HI + r0 + 4]; ah[mf][3] = smu[OFF_A1HI + r1 + 4];
            al[mf][0] = smu[OFF_A1LO + r0];     al[mf][1] = smu[OFF_A1LO + r1];
            al[mf][2] = smu[OFF_A1LO + r0 + 4]; al[mf][3] = smu[OFF_A1LO + r1 + 4];
        }
#pragma unroll
        for (int nf = 0; nf < 4; nf++) {
            int bidx = (kb2 + c4) * 136 + n0 + nf * 8 + g;
            uint32_t bh0 = smu[OFF_B1HI + bidx], bh1 = smu[OFF_B1HI + bidx + 4 * 136];
            uint32_t bl0 = smu[OFF_B1LO + bidx], bl1 = smu[OFF_B1LO + bidx + 4 * 136];
#pragma unroll
            for (int mf = 0; mf < 2; mf++) {
                mma_bf16(acc[mf][nf], ah[mf][0], ah[mf][1], ah[mf][2], ah[mf][3], bh0, bh1);
                mma_bf16(acc[mf][nf], al[mf][0], al[mf][1], al[mf][2], al[mf][3], bh0, bh1);
                mma_bf16(acc[mf][nf], ah[mf][0], ah[mf][1], ah[mf][2], ah[mf][3], bl0, bl1);
            }
        }
    }

    // ---- epilogue 1: raw = (e+be)*q*k, logits, split raw ----
    uint32_t rawh[2][4][2], rawl[2][4][2];
#pragma unroll
    for (int mf = 0; mf < 2; mf++) {
#pragma unroll
        for (int cih = 0; cih < 2; cih++) {
            int r = m0 + mf * 16 + g + cih * 8;
            const float* kr = g_QKV + ((size_t)(b * NN + jbase + r)) * QKVW + CH;
            float lg0 = 0.f, lg1 = 0.f;
#pragma unroll
            for (int nf = 0; nf < 4; nf++) {
                int c = n0 + nf * 8 + 2 * c4;
                float2 kk = *(const float2*)(kr + c);
                float2 qq = *(const float2*)(qs + c);
                float2 bb = *(const float2*)(bes + c);
                float r0 = (acc[mf][nf][cih * 2 + 0] + bb.x) * qq.x * kk.x;
                float r1 = (acc[mf][nf][cih * 2 + 1] + bb.y) * qq.y * kk.y;
                split2(r0, r1, rawh[mf][nf][cih], rawl[mf][nf][cih]);
                float p = r0 + r1;
                if (nf < 2) lg0 += p; else lg1 += p;
            }
            lg0 += __shfl_xor_sync(0xffffffffu, lg0, 1);
            lg0 += __shfl_xor_sync(0xffffffffu, lg0, 2);
            lg1 += __shfl_xor_sync(0xffffffffu, lg1, 1);
            lg1 += __shfl_xor_sync(0xffffffffu, lg1, 2);
            if (c4 == 0) {
                *(float2*)(g_LOG + ((size_t)bi * NN + jbase + r) * NH + 2 * wn) =
                    make_float2(lg0 * 0.25f, lg1 * 0.25f);
            }
        }
    }
    __syncthreads();   // all phase-1 smem reads done before overwrite

#pragma unroll
    for (int mf = 0; mf < 2; mf++)
#pragma unroll
        for (int cih = 0; cih < 2; cih++) {
            int r = m0 + mf * 16 + g + cih * 8;
#pragma unroll
            for (int nf = 0; nf < 4; nf++) {
                int c2 = n0 / 2 + nf * 4 + c4;
                smu[OFF_A2HI + r * 68 + c2] = rawh[mf][nf][cih];
                smu[OFF_A2LO + r * 68 + c2] = rawl[mf][nf][cih];
            }
        }
    __syncthreads();

    // ---- phase 2: edge_out[128,64] = raw[128,128] x Weo ----
    const int wm2 = w & 7, wn2 = w >> 3;
    float o[4][4];
#pragma unroll
    for (int nf = 0; nf < 4; nf++)
#pragma unroll
        for (int i = 0; i < 4; i++) o[nf][i] = 0.f;

#pragma unroll
    for (int ks = 0; ks < 8; ks++) {
        const int kb2 = ks * 8;
        int r0 = (wm2 * 16 + g) * 68 + kb2 + c4;
        int r1 = r0 + 8 * 68;
        uint32_t a0h = smu[OFF_A2HI + r0],     a1h = smu[OFF_A2HI + r1];
        uint32_t a2h = smu[OFF_A2HI + r0 + 4], a3h = smu[OFF_A2HI + r1 + 4];
        uint32_t a0l = smu[OFF_A2LO + r0],     a1l = smu[OFF_A2LO + r1];
        uint32_t a2l = smu[OFF_A2LO + r0 + 4], a3l = smu[OFF_A2LO + r1 + 4];
#pragma unroll
        for (int nf = 0; nf < 4; nf++) {
            int bidx = (kb2 + c4) * 72 + wn2 * 32 + nf * 8 + g;
            uint32_t bh0 = smu[OFF_B2HI + bidx], bh1 = smu[OFF_B2HI + bidx + 4 * 72];
            uint32_t bl0 = smu[OFF_B2LO + bidx], bl1 = smu[OFF_B2LO + bidx + 4 * 72];
            mma_bf16(o[nf], a0h, a1h, a2h, a3h, bh0, bh1);
            mma_bf16(o[nf], a0l, a1l, a2l, a3l, bh0, bh1);
            mma_bf16(o[nf], a0h, a1h, a2h, a3h, bl0, bl1);
        }
    }

    // ---- epilogue 2: + beo, store ----
#pragma unroll
    for (int nf = 0; nf < 4; nf++)
#pragma unroll
        for (int cih = 0; cih < 2; cih++) {
            int r = wm2 * 16 + g + cih * 8;
            int c = wn2 * 32 + nf * 8 + 2 * c4;
            float2 bo = *(const float2*)(beo + c);
            *(float2*)(edge_out + ((size_t)bi * NN + jbase + r) * EH + c) =
                make_float2(o[nf][cih * 2 + 0] + bo.x, o[nf][cih * 2 + 1] + bo.y);
        }
}

// ---------------------------------------------------------------------------
// Kernel C: masked softmax over j, node = att @ v, node_out = node @ Wno + bno
// ---------------------------------------------------------------------------
__global__ void __launch_bounds__(CH) softmax_node_kernel(
    const int* __restrict__ mask,
    const float* __restrict__ Wno, const float* __restrict__ bno,
    float* __restrict__ node_out)
{
    __shared__ float ls[NN * NH];
    __shared__ float node_s[CH];
    __shared__ int msk[NN];

    int bi = blockIdx.x, b = bi >> 9, t = threadIdx.x;

    for (int j = t; j < NN; j += CH) msk[j] = mask[b * NN + j];
    __syncthreads();

    const float4* Lp = (const float4*)(g_LOG + (size_t)bi * NN * NH);
    float4* lsf4 = (float4*)ls;
    for (int fi = t; fi < NN * NH / 4; fi += CH) {
        float4 v = Lp[fi];
        if (!msk[fi >> 1]) { v.x = v.y = v.z = v.w = -FLT_MAX; }
        lsf4[fi] = v;
    }
    __syncthreads();

    int h = t >> 4;
    float m = -FLT_MAX;
    for (int j = 0; j < NN; j++) m = fmaxf(m, ls[j * NH + h]);
    float ssum = 0.f;
    for (int j = 0; j < NN; j++) {
        float p = __expf(ls[j * NH + h] - m);
        ls[j * NH + h] = p;
        ssum += p;
    }
    float inv = 1.f / ssum;
    __syncthreads();

    float acc = 0.f;
    const float* Vp = g_QKV + (b * NN) * QKVW + 2 * CH + t;
    for (int j = 0; j < NN; j++)
        acc = fmaf(ls[j * NH + h], Vp[j * QKVW], acc);
    node_s[t] = acc * inv;
    __syncthreads();

    float o = bno[t];
#pragma unroll 8
    for (int k = 0; k < CH; k++) o = fmaf(node_s[k], Wno[k * CH + t], o);
    node_out[bi * CH + t] = o;
}

// ---------------------------------------------------------------------------
extern "C" void kernel_launch(void* const* d_in, const int* in_sizes, int n_in,
                              void* d_out, int out_size)
{
    const float* x         = (const float*)d_in[0];
    const float* edge_attr = (const float*)d_in[1];
    const int*   mask      = (const int*)d_in[2];
    const float* Wqkv      = (const float*)d_in[3];
    const float* bqkv      = (const float*)d_in[4];
    const float* We        = (const float*)d_in[5];
    const float* be        = (const float*)d_in[6];
    const float* Wno       = (const float*)d_in[7];
    const float* bno       = (const float*)d_in[8];
    const float* Weo       = (const float*)d_in[9];
    const float* beo       = (const float*)d_in[10];

    float* out      = (float*)d_out;
    float* node_out = out;                       // (2,512,128)
    float* edge_out = out + NB * NN * CH;        // (2,512,512,64)

    prep_kernel<<<16, 256>>>(We, Weo);
    qkv_kernel<<<NB * NN, QKVW>>>(x, Wqkv, bqkv);

    size_t shmem = SMEM_U32 * sizeof(uint32_t);  // 109568 B
    cudaFuncSetAttribute(edge_mma_kernel,
                         cudaFuncAttributeMaxDynamicSharedMemorySize, (int)shmem);
    edge_mma_kernel<<<dim3(NN / TJM, NB * NN), 512, shmem>>>(
        edge_attr, be, beo, edge_out);

    softmax_node_kernel<<<NB * NN, CH>>>(mask, Wno, bno, node_out);
}

// round 5
// speedup vs baseline: 2.2006x; 1.7376x over previous
#include <cuda_runtime.h>
#include <cuda_bf16.h>
#include <cstdint>
#include <float.h>

#define NB 2
#define NN 512
#define NH 8
#define CH 128      // n_head * head_hidden
#define EH 64       // edge hidden
#define QKVW 384
#define TJM 128     // j-rows per tile (MMA M)
#define NT (NB * NN * 4)   // 4096 tiles
#define EGRID 148

// Scratch (device globals)
__device__ float g_QKV[NB * NN * QKVW];              // q|k|v per node row
__device__ float g_LOG[(size_t)NB * NN * NN * NH];   // attention logits
// Pre-split weights, packed bf16x2 along K, padded strides (u32 elements)
__device__ uint32_t g_WeHi[32 * 136];   // We  [k2=32][c=128] pad 136
__device__ uint32_t g_WeLo[32 * 136];
__device__ uint32_t g_WeoHi[64 * 72];   // Weo [k2=64][eo=64] pad 72
__device__ uint32_t g_WeoLo[64 * 72];

// ---------------------------------------------------------------------------
// helpers
// ---------------------------------------------------------------------------
__device__ __forceinline__ void split2(float a, float b, uint32_t& hi, uint32_t& lo) {
    __nv_bfloat16 ha = __float2bfloat16_rn(a);
    __nv_bfloat16 hb = __float2bfloat16_rn(b);
    float ra = a - __bfloat162float(ha);
    float rb = b - __bfloat162float(hb);
    __nv_bfloat16 la = __float2bfloat16_rn(ra);
    __nv_bfloat16 lb = __float2bfloat16_rn(rb);
    unsigned short uha = *(unsigned short*)&ha, uhb = *(unsigned short*)&hb;
    unsigned short ula = *(unsigned short*)&la, ulb = *(unsigned short*)&lb;
    hi = ((uint32_t)uhb << 16) | uha;     // low half = even-k element
    lo = ((uint32_t)ulb << 16) | ula;
}

__device__ __forceinline__ void mma_bf16(float* c,
    uint32_t a0, uint32_t a1, uint32_t a2, uint32_t a3,
    uint32_t b0, uint32_t b1)
{
    asm volatile(
        "mma.sync.aligned.m16n8k16.row.col.f32.bf16.bf16.f32 "
        "{%0,%1,%2,%3}, {%4,%5,%6,%7}, {%8,%9}, {%0,%1,%2,%3};"
        : "+f"(c[0]), "+f"(c[1]), "+f"(c[2]), "+f"(c[3])
        : "r"(a0), "r"(a1), "r"(a2), "r"(a3), "r"(b0), "r"(b1));
}

__device__ __forceinline__ uint32_t smem_u32(const void* p) {
    uint32_t a;
    asm("{ .reg .u64 t; cvta.to.shared.u64 t, %1; cvt.u32.u64 %0, t; }"
        : "=r"(a) : "l"(p));
    return a;
}
__device__ __forceinline__ void cp16(uint32_t smaddr, const void* g) {
    asm volatile("cp.async.cg.shared.global [%0], [%1], 16;"
                 :: "r"(smaddr), "l"(g) : "memory");
}
#define CP_COMMIT() asm volatile("cp.async.commit_group;" ::: "memory")
#define CP_WAIT0()  asm volatile("cp.async.wait_group 0;" ::: "memory")

// SMEM map (u32 units)
#define OFF_B1HI 0        // 4352
#define OFF_B1LO 4352     // 4352
#define OFF_B2HI 8704     // 4608
#define OFF_B2LO 13312    // 4608
#define OFF_A1HI 17920    // 4608  (128 x 36)
#define OFF_A1LO 22528    // 4608
#define OFF_A2HI 17920    // 8704  (128 x 68) overlays A1 (dead by then)
#define OFF_A2LO 27136    // 8704
#define OFF_P    35840    // 8192  raw edge tile staging (32 KB)
#define OFF_QS   44032    // 128 floats
#define OFF_BES  44160    // 128 floats
#define SMEM_U32 44288    // 177152 bytes

// ---------------------------------------------------------------------------
// Kernel P: pre-split weights
// ---------------------------------------------------------------------------
__global__ void prep_kernel(const float* __restrict__ We, const float* __restrict__ Weo) {
    int t = blockIdx.x * 256 + threadIdx.x;
    if (t < 32 * 128) {
        int k2 = t >> 7, c = t & 127;
        uint32_t h, l;
        split2(We[(2 * k2) * CH + c], We[(2 * k2 + 1) * CH + c], h, l);
        g_WeHi[k2 * 136 + c] = h; g_WeLo[k2 * 136 + c] = l;
    }
    if (t < 64 * 64) {
        int k2 = t >> 6, eo = t & 63;
        uint32_t h, l;
        split2(Weo[(2 * k2) * EH + eo], Weo[(2 * k2 + 1) * EH + eo], h, l);
        g_WeoHi[k2 * 72 + eo] = h; g_WeoLo[k2 * 72 + eo] = l;
    }
}

// ---------------------------------------------------------------------------
// Kernel A: qkv = x @ Wqkv + bqkv
// ---------------------------------------------------------------------------
__global__ void __launch_bounds__(QKVW) qkv_kernel(
    const float* __restrict__ x, const float* __restrict__ W,
    const float* __restrict__ bias)
{
    __shared__ float xs[CH];
    int row = blockIdx.x, col = threadIdx.x;
    if (col < CH) xs[col] = x[row * CH + col];
    __syncthreads();
    float acc = bias[col];
#pragma unroll 16
    for (int k = 0; k < CH; k++) acc = fmaf(xs[k], W[k * QKVW + col], acc);
    g_QKV[row * QKVW + col] = acc;
}

// ---------------------------------------------------------------------------
// Kernel B: persistent fused edge pipeline, mma.sync bf16 3-term split.
// Grid 148, 512 threads. Weights loaded once; edge tiles double-staged
// via cp.async.
// ---------------------------------------------------------------------------
__global__ void __launch_bounds__(512) edge_mma_kernel(
    const float* __restrict__ edge_attr,
    const float* __restrict__ be, const float* __restrict__ beo,
    float* __restrict__ edge_out)
{
    extern __shared__ uint32_t smu[];
    float* qs  = (float*)(smu + OFF_QS);
    float* bes = (float*)(smu + OFF_BES);
    const uint32_t p_sm = smem_u32(smu) + OFF_P * 4;

    const int t = threadIdx.x, lane = t & 31, w = t >> 5;
    const int g = lane >> 2, c4 = lane & 3;
    const int wm = w & 3, wn = w >> 2;
    const int m0 = wm * 32, n0 = wn * 32;
    const int wm2 = w & 7, wn2 = w >> 3;

    // ---- one-time loads: weights + bias ----
    for (int i = t; i < 32 * 136; i += 512) {
        smu[OFF_B1HI + i] = g_WeHi[i];
        smu[OFF_B1LO + i] = g_WeLo[i];
    }
    for (int i = t; i < 64 * 72; i += 512) {
        smu[OFF_B2HI + i] = g_WeoHi[i];
        smu[OFF_B2LO + i] = g_WeoLo[i];
    }
    if (t < CH) bes[t] = be[t];

    // ---- prefetch first tile ----
    int tile = blockIdx.x;
    if (tile < NT) {
        int bi = tile >> 2, jt = tile & 3;
        const float4* src = (const float4*)(edge_attr + ((size_t)bi * NN + jt * TJM) * EH);
#pragma unroll
        for (int s = 0; s < 4; s++) {
            int fi = t + s * 512;
            cp16(p_sm + fi * 16, src + fi);
        }
    }
    CP_COMMIT();

    for (; tile < NT; tile += EGRID) {
        const int bi = tile >> 2, jt = tile & 3;
        const int b = bi >> 9, jbase = jt * TJM;

        CP_WAIT0();
        __syncthreads();       // staging P valid; previous tile fully done

        // ---- split staged tile -> A1 limbs; load q row ----
        {
            const float4* Pf4 = (const float4*)(smu + OFF_P);
#pragma unroll
            for (int s = 0; s < 4; s++) {
                int fi = t + s * 512;
                int row = fi >> 4, cc4 = fi & 15;
                float4 v = Pf4[fi];
                uint32_t h0, l0, h1, l1;
                split2(v.x, v.y, h0, l0);
                split2(v.z, v.w, h1, l1);
                int idx = row * 36 + cc4 * 2;
                smu[OFF_A1HI + idx]     = h0;
                smu[OFF_A1HI + idx + 1] = h1;
                smu[OFF_A1LO + idx]     = l0;
                smu[OFF_A1LO + idx + 1] = l1;
            }
            if (t < CH) qs[t] = g_QKV[bi * QKVW + t];
        }
        __syncthreads();       // A1/qs ready; staging consumed

        // ---- prefetch next tile into staging ----
        {
            int nt2 = tile + EGRID;
            if (nt2 < NT) {
                int nbi = nt2 >> 2, njt = nt2 & 3;
                const float4* src = (const float4*)(edge_attr + ((size_t)nbi * NN + njt * TJM) * EH);
#pragma unroll
                for (int s = 0; s < 4; s++) {
                    int fi = t + s * 512;
                    cp16(p_sm + fi * 16, src + fi);
                }
            }
            CP_COMMIT();
        }

        // ---- phase 1: e[128,128] = A1[128,64] x We ----
        float acc[2][4][4];
#pragma unroll
        for (int mf = 0; mf < 2; mf++)
#pragma unroll
            for (int nf = 0; nf < 4; nf++)
#pragma unroll
                for (int i = 0; i < 4; i++) acc[mf][nf][i] = 0.f;

#pragma unroll
        for (int ks = 0; ks < 4; ks++) {
            const int kb2 = ks * 8;
            uint32_t ah[2][4], al[2][4];
#pragma unroll
            for (int mf = 0; mf < 2; mf++) {
                int r0 = (m0 + mf * 16 + g) * 36 + kb2 + c4;
                int r1 = r0 + 8 * 36;
                ah[mf][0] = smu[OFF_A1HI + r0];     ah[mf][1] = smu[OFF_A1HI + r1];
                ah[mf][2] = smu[OFF_A1HI + r0 + 4]; ah[mf][3] = smu[OFF_A1HI + r1 + 4];
                al[mf][0] = smu[OFF_A1LO + r0];     al[mf][1] = smu[OFF_A1LO + r1];
                al[mf][2] = smu[OFF_A1LO + r0 + 4]; al[mf][3] = smu[OFF_A1LO + r1 + 4];
            }
#pragma unroll
            for (int nf = 0; nf < 4; nf++) {
                int bidx = (kb2 + c4) * 136 + n0 + nf * 8 + g;
                uint32_t bh0 = smu[OFF_B1HI + bidx], bh1 = smu[OFF_B1HI + bidx + 4 * 136];
                uint32_t bl0 = smu[OFF_B1LO + bidx], bl1 = smu[OFF_B1LO + bidx + 4 * 136];
#pragma unroll
                for (int mf = 0; mf < 2; mf++) {
                    mma_bf16(acc[mf][nf], ah[mf][0], ah[mf][1], ah[mf][2], ah[mf][3], bh0, bh1);
                    mma_bf16(acc[mf][nf], al[mf][0], al[mf][1], al[mf][2], al[mf][3], bh0, bh1);
                    mma_bf16(acc[mf][nf], ah[mf][0], ah[mf][1], ah[mf][2], ah[mf][3], bl0, bl1);
                }
            }
        }

        // ---- epilogue 1: raw = (e+be)*q*k, logits, split raw ----
        uint32_t rawh[2][4][2], rawl[2][4][2];
#pragma unroll
        for (int mf = 0; mf < 2; mf++) {
#pragma unroll
            for (int cih = 0; cih < 2; cih++) {
                int r = m0 + mf * 16 + g + cih * 8;
                const float* kr = g_QKV + ((size_t)(b * NN + jbase + r)) * QKVW + CH;
                float lg0 = 0.f, lg1 = 0.f;
#pragma unroll
                for (int nf = 0; nf < 4; nf++) {
                    int c = n0 + nf * 8 + 2 * c4;
                    float2 kk = *(const float2*)(kr + c);
                    float2 qq = *(const float2*)(qs + c);
                    float2 bb = *(const float2*)(bes + c);
                    float r0 = (acc[mf][nf][cih * 2 + 0] + bb.x) * qq.x * kk.x;
                    float r1 = (acc[mf][nf][cih * 2 + 1] + bb.y) * qq.y * kk.y;
                    split2(r0, r1, rawh[mf][nf][cih], rawl[mf][nf][cih]);
                    float p = r0 + r1;
                    if (nf < 2) lg0 += p; else lg1 += p;
                }
                lg0 += __shfl_xor_sync(0xffffffffu, lg0, 1);
                lg0 += __shfl_xor_sync(0xffffffffu, lg0, 2);
                lg1 += __shfl_xor_sync(0xffffffffu, lg1, 1);
                lg1 += __shfl_xor_sync(0xffffffffu, lg1, 2);
                if (c4 == 0) {
                    *(float2*)(g_LOG + ((size_t)bi * NN + jbase + r) * NH + 2 * wn) =
                        make_float2(lg0 * 0.25f, lg1 * 0.25f);
                }
            }
        }
        __syncthreads();   // all phase-1 smem reads done before A2 overlay write

#pragma unroll
        for (int mf = 0; mf < 2; mf++)
#pragma unroll
            for (int cih = 0; cih < 2; cih++) {
                int r = m0 + mf * 16 + g + cih * 8;
#pragma unroll
                for (int nf = 0; nf < 4; nf++) {
                    int c2 = n0 / 2 + nf * 4 + c4;
                    smu[OFF_A2HI + r * 68 + c2] = rawh[mf][nf][cih];
                    smu[OFF_A2LO + r * 68 + c2] = rawl[mf][nf][cih];
                }
            }
        __syncthreads();

        // ---- phase 2: edge_out[128,64] = raw[128,128] x Weo ----
        float o[4][4];
#pragma unroll
        for (int nf = 0; nf < 4; nf++)
#pragma unroll
            for (int i = 0; i < 4; i++) o[nf][i] = 0.f;

#pragma unroll
        for (int ks = 0; ks < 8; ks++) {
            const int kb2 = ks * 8;
            int r0 = (wm2 * 16 + g) * 68 + kb2 + c4;
            int r1 = r0 + 8 * 68;
            uint32_t a0h = smu[OFF_A2HI + r0],     a1h = smu[OFF_A2HI + r1];
            uint32_t a2h = smu[OFF_A2HI + r0 + 4], a3h = smu[OFF_A2HI + r1 + 4];
            uint32_t a0l = smu[OFF_A2LO + r0],     a1l = smu[OFF_A2LO + r1];
            uint32_t a2l = smu[OFF_A2LO + r0 + 4], a3l = smu[OFF_A2LO + r1 + 4];
#pragma unroll
            for (int nf = 0; nf < 4; nf++) {
                int bidx = (kb2 + c4) * 72 + wn2 * 32 + nf * 8 + g;
                uint32_t bh0 = smu[OFF_B2HI + bidx], bh1 = smu[OFF_B2HI + bidx + 4 * 72];
                uint32_t bl0 = smu[OFF_B2LO + bidx], bl1 = smu[OFF_B2LO + bidx + 4 * 72];
                mma_bf16(o[nf], a0h, a1h, a2h, a3h, bh0, bh1);
                mma_bf16(o[nf], a0l, a1l, a2l, a3l, bh0, bh1);
                mma_bf16(o[nf], a0h, a1h, a2h, a3h, bl0, bl1);
            }
        }

        // ---- epilogue 2: + beo, store ----
#pragma unroll
        for (int nf = 0; nf < 4; nf++)
#pragma unroll
            for (int cih = 0; cih < 2; cih++) {
                int r = wm2 * 16 + g + cih * 8;
                int c = wn2 * 32 + nf * 8 + 2 * c4;
                float2 bo = *(const float2*)(beo + c);
                *(float2*)(edge_out + ((size_t)bi * NN + jbase + r) * EH + c) =
                    make_float2(o[nf][cih * 2 + 0] + bo.x, o[nf][cih * 2 + 1] + bo.y);
            }
    }
}

// ---------------------------------------------------------------------------
// Kernel C: masked softmax over j, node = att @ v, node_out = node @ Wno + bno
// 256 threads: warp-per-head softmax + split-j attention*V.
// ---------------------------------------------------------------------------
__global__ void __launch_bounds__(256) softmax_node_kernel(
    const int* __restrict__ mask,
    const float* __restrict__ Wno, const float* __restrict__ bno,
    float* __restrict__ node_out)
{
    __shared__ float ls[NN * 9];      // stride 9: conflict-free column walks
    __shared__ float partial[2 * CH];
    __shared__ float node_s[CH];
    __shared__ float invs[NH];
    __shared__ int msk[NN];

    int bi = blockIdx.x, b = bi >> 9, t = threadIdx.x;

    for (int j = t; j < NN; j += 256) msk[j] = mask[b * NN + j];
    __syncthreads();

    // load logits, apply mask, scatter to stride-9 layout
    const float4* Lp = (const float4*)(g_LOG + (size_t)bi * NN * NH);
    for (int fi = t; fi < NN * NH / 4; fi += 256) {
        float4 v = Lp[fi];
        int j = fi >> 1, hb = (fi & 1) * 4;
        if (!msk[j]) { v.x = v.y = v.z = v.w = -FLT_MAX; }
        ls[j * 9 + hb + 0] = v.x;
        ls[j * 9 + hb + 1] = v.y;
        ls[j * 9 + hb + 2] = v.z;
        ls[j * 9 + hb + 3] = v.w;
    }
    __syncthreads();

    // softmax: warp wH owns head wH
    {
        int wH = t >> 5, l = t & 31;
        float m = -FLT_MAX;
#pragma unroll
        for (int k = 0; k < 16; k++)
            m = fmaxf(m, ls[(l + 32 * k) * 9 + wH]);
#pragma unroll
        for (int off = 16; off; off >>= 1)
            m = fmaxf(m, __shfl_xor_sync(0xffffffffu, m, off));
        float s = 0.f;
#pragma unroll
        for (int k = 0; k < 16; k++) {
            int j = l + 32 * k;
            float p = __expf(ls[j * 9 + wH] - m);
            ls[j * 9 + wH] = p;
            s += p;
        }
#pragma unroll
        for (int off = 16; off; off >>= 1)
            s += __shfl_xor_sync(0xffffffffu, s, off);
        if (l == 0) invs[wH] = 1.f / s;
    }
    __syncthreads();

    // attention * V, split over two j-halves
    {
        int half = t >> 7, c = t & 127, h = c >> 4;
        const float* Vp = g_QKV + (size_t)(b * NN + half * 256) * QKVW + 2 * CH + c;
        const float* lsp = ls + (half * 256) * 9 + h;
        float a0 = 0.f, a1 = 0.f;
#pragma unroll 4
        for (int j = 0; j < 256; j += 2) {
            a0 = fmaf(lsp[j * 9],       Vp[(size_t)j * QKVW],       a0);
            a1 = fmaf(lsp[(j + 1) * 9], Vp[(size_t)(j + 1) * QKVW], a1);
        }
        partial[half * CH + c] = a0 + a1;
    }
    __syncthreads();

    if (t < CH) node_s[t] = (partial[t] + partial[CH + t]) * invs[t >> 4];
    __syncthreads();

    if (t < CH) {
        float o = bno[t];
#pragma unroll 8
        for (int k = 0; k < CH; k++) o = fmaf(node_s[k], Wno[k * CH + t], o);
        node_out[bi * CH + t] = o;
    }
}

// ---------------------------------------------------------------------------
extern "C" void kernel_launch(void* const* d_in, const int* in_sizes, int n_in,
                              void* d_out, int out_size)
{
    const float* x         = (const float*)d_in[0];
    const float* edge_attr = (const float*)d_in[1];
    const int*   mask      = (const int*)d_in[2];
    const float* Wqkv      = (const float*)d_in[3];
    const float* bqkv      = (const float*)d_in[4];
    const float* We        = (const float*)d_in[5];
    const float* be        = (const float*)d_in[6];
    const float* Wno       = (const float*)d_in[7];
    const float* bno       = (const float*)d_in[8];
    const float* Weo       = (const float*)d_in[9];
    const float* beo       = (const float*)d_in[10];

    float* out      = (float*)d_out;
    float* node_out = out;                       // (2,512,128)
    float* edge_out = out + NB * NN * CH;        // (2,512,512,64)

    prep_kernel<<<16, 256>>>(We, Weo);
    qkv_kernel<<<NB * NN, QKVW>>>(x, Wqkv, bqkv);

    size_t shmem = SMEM_U32 * sizeof(uint32_t);  // 177152 B
    cudaFuncSetAttribute(edge_mma_kernel,
                         cudaFuncAttributeMaxDynamicSharedMemorySize, (int)shmem);
    edge_mma_kernel<<<EGRID, 512, shmem>>>(edge_attr, be, beo, edge_out);

    softmax_node_kernel<<<NB * NN, 256>>>(mask, Wno, bno, node_out);
}

// round 6
// speedup vs baseline: 2.3951x; 1.0884x over previous
#include <cuda_runtime.h>
#include <cuda_bf16.h>
#include <cstdint>
#include <float.h>

#define NB 2
#define NN 512
#define NH 8
#define CH 128      // n_head * head_hidden
#define EH 64       // edge hidden
#define QKVW 384
#define TJM 128     // j-rows per tile (MMA M)
#define NT (NB * NN * 4)   // 4096 tiles
#define EGRID 148

// Scratch (device globals)
__device__ float g_QKV[NB * NN * QKVW];              // q|k|v per node row
__device__ float g_LOG[(size_t)NB * NN * NN * NH];   // attention logits
// tf32(rna) weights, padded strides (u32 elements)
__device__ uint32_t g_We1[64 * 136];    // We  [k=64][c=128]  stride 136
__device__ uint32_t g_Weo1[128 * 72];   // Weo [k=128][eo=64] stride 72

// ---------------------------------------------------------------------------
// helpers
// ---------------------------------------------------------------------------
__device__ __forceinline__ uint32_t f2tf(float f) {
    uint32_t r;
    asm("cvt.rna.tf32.f32 %0, %1;" : "=r"(r) : "f"(f));
    return r;
}

__device__ __forceinline__ void mma_tf32(float* c,
    uint32_t a0, uint32_t a1, uint32_t a2, uint32_t a3,
    uint32_t b0, uint32_t b1)
{
    asm volatile(
        "mma.sync.aligned.m16n8k8.row.col.f32.tf32.tf32.f32 "
        "{%0,%1,%2,%3}, {%4,%5,%6,%7}, {%8,%9}, {%0,%1,%2,%3};"
        : "+f"(c[0]), "+f"(c[1]), "+f"(c[2]), "+f"(c[3])
        : "r"(a0), "r"(a1), "r"(a2), "r"(a3), "r"(b0), "r"(b1));
}

__device__ __forceinline__ uint32_t smem_u32(const void* p) {
    uint32_t a;
    asm("{ .reg .u64 t; cvta.to.shared.u64 t, %1; cvt.u32.u64 %0, t; }"
        : "=r"(a) : "l"(p));
    return a;
}
__device__ __forceinline__ void cp16(uint32_t smaddr, const void* g) {
    asm volatile("cp.async.cg.shared.global [%0], [%1], 16;"
                 :: "r"(smaddr), "l"(g) : "memory");
}
#define CP_COMMIT() asm volatile("cp.async.commit_group;" ::: "memory")
#define CP_WAIT0()  asm volatile("cp.async.wait_group 0;" ::: "memory")

// SMEM map (u32 units). A1 (stride 68) overlays A2 (stride 132) — A1 is
// dead once phase-1 fragments are consumed, enforced by __syncthreads.
#define OFF_B1   0        // 8704  We  [64][136]
#define OFF_B2   8704     // 9216  Weo [128][72]
#define OFF_A2   17920    // 16896 raw [128][132]  (A1 [128][68] same base)
#define OFF_A1   17920
#define OFF_P    34816    // 8192  fp32 edge tile staging
#define OFF_QS   43008    // 128 floats
#define OFF_BES  43136    // 128 floats
#define SMEM_U32 43264    // 173056 bytes

// ---------------------------------------------------------------------------
// Kernel P: weights -> tf32(rna), padded layouts
// ---------------------------------------------------------------------------
__global__ void prep_kernel(const float* __restrict__ We, const float* __restrict__ Weo) {
    int t = blockIdx.x * 256 + threadIdx.x;   // 0..8191
    {   // We: [64][128] row-major -> g_We1 [k][c] stride 136
        int k = t >> 7, c = t & 127;
        g_We1[k * 136 + c] = f2tf(We[k * CH + c]);
    }
    {   // Weo: [128][64] row-major -> g_Weo1 [k][eo] stride 72
        int k = t >> 6, eo = t & 63;
        g_Weo1[k * 72 + eo] = f2tf(Weo[k * EH + eo]);
    }
}

// ---------------------------------------------------------------------------
// Kernel A: qkv = x @ Wqkv + bqkv  (exact fp32)
// ---------------------------------------------------------------------------
__global__ void __launch_bounds__(QKVW) qkv_kernel(
    const float* __restrict__ x, const float* __restrict__ W,
    const float* __restrict__ bias)
{
    __shared__ float xs[CH];
    int row = blockIdx.x, col = threadIdx.x;
    if (col < CH) xs[col] = x[row * CH + col];
    __syncthreads();
    float acc = bias[col];
#pragma unroll 16
    for (int k = 0; k < CH; k++) acc = fmaf(xs[k], W[k * QKVW + col], acc);
    g_QKV[row * QKVW + col] = acc;
}

// ---------------------------------------------------------------------------
// Kernel B: persistent fused edge pipeline, single-pass tf32 mma.
// Grid 148, 512 threads. Weights resident; edge tiles prefetched (cp.async).
// ---------------------------------------------------------------------------
__global__ void __launch_bounds__(512) edge_mma_kernel(
    const float* __restrict__ edge_attr,
    const float* __restrict__ be, const float* __restrict__ beo,
    float* __restrict__ edge_out)
{
    extern __shared__ uint32_t smu[];
    float* qs  = (float*)(smu + OFF_QS);
    float* bes = (float*)(smu + OFF_BES);
    const uint32_t p_sm = smem_u32(smu) + OFF_P * 4;

    const int t = threadIdx.x, lane = t & 31, w = t >> 5;
    const int g = lane >> 2, c4 = lane & 3;
    const int wm = w & 3, wn = w >> 2;
    const int m0 = wm * 32, n0 = wn * 32;
    const int wm2 = w & 7, wn2 = w >> 3;

    // ---- one-time loads: tf32 weights + bias ----
    for (int i = t; i < 64 * 136; i += 512) smu[OFF_B1 + i] = g_We1[i];
    for (int i = t; i < 128 * 72; i += 512) smu[OFF_B2 + i] = g_Weo1[i];
    if (t < CH) bes[t] = be[t];

    // ---- prefetch first tile ----
    int tile = blockIdx.x;
    if (tile < NT) {
        int bi = tile >> 2, jt = tile & 3;
        const float4* src = (const float4*)(edge_attr + ((size_t)bi * NN + jt * TJM) * EH);
#pragma unroll
        for (int s = 0; s < 4; s++) {
            int fi = t + s * 512;
            cp16(p_sm + fi * 16, src + fi);
        }
    }
    CP_COMMIT();

    for (; tile < NT; tile += EGRID) {
        const int bi = tile >> 2, jt = tile & 3;
        const int b = bi >> 9, jbase = jt * TJM;

        CP_WAIT0();
        __syncthreads();       // staging valid; prior tile's A2 reads done

        // ---- copy staged tile -> A1 with rna-tf32 rounding; q row ----
        {
            const float4* Pf4 = (const float4*)(smu + OFF_P);
#pragma unroll
            for (int s = 0; s < 4; s++) {
                int fi = t + s * 512;              // 2048 float4
                int row = fi >> 4, q4 = fi & 15;
                float4 v = Pf4[fi];
                int idx = OFF_A1 + row * 68 + q4 * 4;
                smu[idx]     = f2tf(v.x);
                smu[idx + 1] = f2tf(v.y);
                smu[idx + 2] = f2tf(v.z);
                smu[idx + 3] = f2tf(v.w);
            }
            if (t < CH) qs[t] = g_QKV[bi * QKVW + t];
        }
        __syncthreads();       // A1/qs ready; staging consumed

        // ---- prefetch next tile ----
        {
            int nt2 = tile + EGRID;
            if (nt2 < NT) {
                int nbi = nt2 >> 2, njt = nt2 & 3;
                const float4* src = (const float4*)(edge_attr + ((size_t)nbi * NN + njt * TJM) * EH);
#pragma unroll
                for (int s = 0; s < 4; s++) {
                    int fi = t + s * 512;
                    cp16(p_sm + fi * 16, src + fi);
                }
            }
            CP_COMMIT();
        }

        // ---- phase 1: e[128,128] = A1[128,64] x We, 8 tf32 k-steps ----
        float acc[2][4][4];
#pragma unroll
        for (int mf = 0; mf < 2; mf++)
#pragma unroll
            for (int nf = 0; nf < 4; nf++)
#pragma unroll
                for (int i = 0; i < 4; i++) acc[mf][nf][i] = 0.f;

#pragma unroll
        for (int ks = 0; ks < 8; ks++) {
            const int kb = ks * 8;
            uint32_t a[2][4];
#pragma unroll
            for (int mf = 0; mf < 2; mf++) {
                int r0 = OFF_A1 + (m0 + mf * 16 + g) * 68 + kb + c4;
                int r1 = r0 + 8 * 68;
                a[mf][0] = smu[r0];     a[mf][1] = smu[r1];
                a[mf][2] = smu[r0 + 4]; a[mf][3] = smu[r1 + 4];
            }
#pragma unroll
            for (int nf = 0; nf < 4; nf++) {
                int bidx = OFF_B1 + (kb + c4) * 136 + n0 + nf * 8 + g;
                uint32_t b0 = smu[bidx], b1 = smu[bidx + 4 * 136];
#pragma unroll
                for (int mf = 0; mf < 2; mf++)
                    mma_tf32(acc[mf][nf], a[mf][0], a[mf][1], a[mf][2], a[mf][3], b0, b1);
            }
        }

        // ---- epilogue 1: raw = (e+be)*q*k (fp32 in acc), logits ----
#pragma unroll
        for (int mf = 0; mf < 2; mf++) {
#pragma unroll
            for (int cih = 0; cih < 2; cih++) {
                int r = m0 + mf * 16 + g + cih * 8;
                const float* kr = g_QKV + ((size_t)(b * NN + jbase + r)) * QKVW + CH;
                float lg0 = 0.f, lg1 = 0.f;
#pragma unroll
                for (int nf = 0; nf < 4; nf++) {
                    int c = n0 + nf * 8 + 2 * c4;
                    float2 kk = *(const float2*)(kr + c);
                    float2 qq = *(const float2*)(qs + c);
                    float2 bb = *(const float2*)(bes + c);
                    float r0 = (acc[mf][nf][cih * 2 + 0] + bb.x) * qq.x * kk.x;
                    float r1 = (acc[mf][nf][cih * 2 + 1] + bb.y) * qq.y * kk.y;
                    acc[mf][nf][cih * 2 + 0] = r0;
                    acc[mf][nf][cih * 2 + 1] = r1;
                    float p = r0 + r1;
                    if (nf < 2) lg0 += p; else lg1 += p;
                }
                lg0 += __shfl_xor_sync(0xffffffffu, lg0, 1);
                lg0 += __shfl_xor_sync(0xffffffffu, lg0, 2);
                lg1 += __shfl_xor_sync(0xffffffffu, lg1, 1);
                lg1 += __shfl_xor_sync(0xffffffffu, lg1, 2);
                if (c4 == 0) {
                    *(float2*)(g_LOG + ((size_t)bi * NN + jbase + r) * NH + 2 * wn) =
                        make_float2(lg0 * 0.25f, lg1 * 0.25f);
                }
            }
        }
        __syncthreads();   // all phase-1 A1 reads done before A2 overlay write

        // ---- store raw as rna-tf32 into A2 [128][132] ----
#pragma unroll
        for (int mf = 0; mf < 2; mf++)
#pragma unroll
            for (int cih = 0; cih < 2; cih++) {
                int r = m0 + mf * 16 + g + cih * 8;
#pragma unroll
                for (int nf = 0; nf < 4; nf++) {
                    int c = n0 + nf * 8 + 2 * c4;
                    int idx = OFF_A2 + r * 132 + c;
                    smu[idx]     = f2tf(acc[mf][nf][cih * 2 + 0]);
                    smu[idx + 1] = f2tf(acc[mf][nf][cih * 2 + 1]);
                }
            }
        __syncthreads();

        // ---- phase 2: edge_out[128,64] = raw[128,128] x Weo, 16 k-steps ----
        float o[4][4];
#pragma unroll
        for (int nf = 0; nf < 4; nf++)
#pragma unroll
            for (int i = 0; i < 4; i++) o[nf][i] = 0.f;

#pragma unroll
        for (int ks = 0; ks < 16; ks++) {
            const int kb = ks * 8;
            int r0 = OFF_A2 + (wm2 * 16 + g) * 132 + kb + c4;
            int r1 = r0 + 8 * 132;
            uint32_t a0 = smu[r0],     a1 = smu[r1];
            uint32_t a2 = smu[r0 + 4], a3 = smu[r1 + 4];
#pragma unroll
            for (int nf = 0; nf < 4; nf++) {
                int bidx = OFF_B2 + (kb + c4) * 72 + wn2 * 32 + nf * 8 + g;
                uint32_t b0 = smu[bidx], b1 = smu[bidx + 4 * 72];
                mma_tf32(o[nf], a0, a1, a2, a3, b0, b1);
            }
        }

        // ---- epilogue 2: + beo, store ----
#pragma unroll
        for (int nf = 0; nf < 4; nf++)
#pragma unroll
            for (int cih = 0; cih < 2; cih++) {
                int r = wm2 * 16 + g + cih * 8;
                int c = wn2 * 32 + nf * 8 + 2 * c4;
                float2 bo = *(const float2*)(beo + c);
                *(float2*)(edge_out + ((size_t)bi * NN + jbase + r) * EH + c) =
                    make_float2(o[nf][cih * 2 + 0] + bo.x, o[nf][cih * 2 + 1] + bo.y);
            }
    }
}

// ---------------------------------------------------------------------------
// Kernel C: masked softmax over j, node = att @ v, node_out = node @ Wno + bno
// ---------------------------------------------------------------------------
__global__ void __launch_bounds__(256) softmax_node_kernel(
    const int* __restrict__ mask,
    const float* __restrict__ Wno, const float* __restrict__ bno,
    float* __restrict__ node_out)
{
    __shared__ float ls[NN * 9];      // stride 9: conflict-free column walks
    __shared__ float partial[2 * CH];
    __shared__ float node_s[CH];
    __shared__ float invs[NH];
    __shared__ int msk[NN];

    int bi = blockIdx.x, b = bi >> 9, t = threadIdx.x;

    for (int j = t; j < NN; j += 256) msk[j] = mask[b * NN + j];
    __syncthreads();

    const float4* Lp = (const float4*)(g_LOG + (size_t)bi * NN * NH);
    for (int fi = t; fi < NN * NH / 4; fi += 256) {
        float4 v = Lp[fi];
        int j = fi >> 1, hb = (fi & 1) * 4;
        if (!msk[j]) { v.x = v.y = v.z = v.w = -FLT_MAX; }
        ls[j * 9 + hb + 0] = v.x;
        ls[j * 9 + hb + 1] = v.y;
        ls[j * 9 + hb + 2] = v.z;
        ls[j * 9 + hb + 3] = v.w;
    }
    __syncthreads();

    {   // softmax: warp wH owns head wH
        int wH = t >> 5, l = t & 31;
        float m = -FLT_MAX;
#pragma unroll
        for (int k = 0; k < 16; k++)
            m = fmaxf(m, ls[(l + 32 * k) * 9 + wH]);
#pragma unroll
        for (int off = 16; off; off >>= 1)
            m = fmaxf(m, __shfl_xor_sync(0xffffffffu, m, off));
        float s = 0.f;
#pragma unroll
        for (int k = 0; k < 16; k++) {
            int j = l + 32 * k;
            float p = __expf(ls[j * 9 + wH] - m);
            ls[j * 9 + wH] = p;
            s += p;
        }
#pragma unroll
        for (int off = 16; off; off >>= 1)
            s += __shfl_xor_sync(0xffffffffu, s, off);
        if (l == 0) invs[wH] = 1.f / s;
    }
    __syncthreads();

    {   // attention * V, split over two j-halves
        int half = t >> 7, c = t & 127, h = c >> 4;
        const float* Vp = g_QKV + (size_t)(b * NN + half * 256) * QKVW + 2 * CH + c;
        const float* lsp = ls + (half * 256) * 9 + h;
        float a0 = 0.f, a1 = 0.f;
#pragma unroll 4
        for (int j = 0; j < 256; j += 2) {
            a0 = fmaf(lsp[j * 9],       Vp[(size_t)j * QKVW],       a0);
            a1 = fmaf(lsp[(j + 1) * 9], Vp[(size_t)(j + 1) * QKVW], a1);
        }
        partial[half * CH + c] = a0 + a1;
    }
    __syncthreads();

    if (t < CH) node_s[t] = (partial[t] + partial[CH + t]) * invs[t >> 4];
    __syncthreads();

    if (t < CH) {
        float o = bno[t];
#pragma unroll 8
        for (int k = 0; k < CH; k++) o = fmaf(node_s[k], Wno[k * CH + t], o);
        node_out[bi * CH + t] = o;
    }
}

// ---------------------------------------------------------------------------
extern "C" void kernel_launch(void* const* d_in, const int* in_sizes, int n_in,
                              void* d_out, int out_size)
{
    const float* x         = (const float*)d_in[0];
    const float* edge_attr = (const float*)d_in[1];
    const int*   mask      = (const int*)d_in[2];
    const float* Wqkv      = (const float*)d_in[3];
    const float* bqkv      = (const float*)d_in[4];
    const float* We        = (const float*)d_in[5];
    const float* be        = (const float*)d_in[6];
    const float* Wno       = (const float*)d_in[7];
    const float* bno       = (const float*)d_in[8];
    const float* Weo       = (const float*)d_in[9];
    const float* beo       = (const float*)d_in[10];

    float* out      = (float*)d_out;
    float* node_out = out;                       // (2,512,128)
    float* edge_out = out + NB * NN * CH;        // (2,512,512,64)

    prep_kernel<<<32, 256>>>(We, Weo);
    qkv_kernel<<<NB * NN, QKVW>>>(x, Wqkv, bqkv);

    size_t shmem = SMEM_U32 * sizeof(uint32_t);  // 173056 B
    cudaFuncSetAttribute(edge_mma_kernel,
                         cudaFuncAttributeMaxDynamicSharedMemorySize, (int)shmem);
    edge_mma_kernel<<<EGRID, 512, shmem>>>(edge_attr, be, beo, edge_out);

    softmax_node_kernel<<<NB * NN, 256>>>(mask, Wno, bno, node_out);
}

// round 7
// speedup vs baseline: 2.6502x; 1.1065x over previous
#include <cuda_runtime.h>
#include <cuda_bf16.h>
#include <cstdint>
#include <float.h>

#define NB 2
#define NN 512
#define NH 8
#define CH 128      // n_head * head_hidden
#define EH 64       // edge hidden
#define QKVW 384
#define TJM 128     // j-rows per tile (MMA M)
#define NT (NB * NN * 4)   // 4096 tiles
#define EGRID 148

// Scratch (device globals)
__device__ float g_QKV[NB * NN * QKVW];              // q|k|v per node row
__device__ float g_LOG[(size_t)NB * NN * NN * NH];   // attention logits
__device__ uint32_t g_We1[64 * 136];                 // tf32 We [k=64][c=128] stride 136

// ---------------------------------------------------------------------------
// helpers
// ---------------------------------------------------------------------------
__device__ __forceinline__ uint32_t f2tf(float f) {
    uint32_t r;
    asm("cvt.rna.tf32.f32 %0, %1;" : "=r"(r) : "f"(f));
    return r;
}

__device__ __forceinline__ void mma_tf32(float* c,
    uint32_t a0, uint32_t a1, uint32_t a2, uint32_t a3,
    uint32_t b0, uint32_t b1)
{
    asm volatile(
        "mma.sync.aligned.m16n8k8.row.col.f32.tf32.tf32.f32 "
        "{%0,%1,%2,%3}, {%4,%5,%6,%7}, {%8,%9}, {%0,%1,%2,%3};"
        : "+f"(c[0]), "+f"(c[1]), "+f"(c[2]), "+f"(c[3])
        : "r"(a0), "r"(a1), "r"(a2), "r"(a3), "r"(b0), "r"(b1));
}

__device__ __forceinline__ uint32_t smem_u32(const void* p) {
    uint32_t a;
    asm("{ .reg .u64 t; cvta.to.shared.u64 t, %1; cvt.u32.u64 %0, t; }"
        : "=r"(a) : "l"(p));
    return a;
}
__device__ __forceinline__ void cp16(uint32_t smaddr, const void* g) {
    asm volatile("cp.async.cg.shared.global [%0], [%1], 16;"
                 :: "r"(smaddr), "l"(g) : "memory");
}
#define CP_COMMIT() asm volatile("cp.async.commit_group;" ::: "memory")
#define CP_WAIT0()  asm volatile("cp.async.wait_group 0;" ::: "memory")

// SMEM map (u32 units). A1 (stride 68) overlays A2 (stride 132) — A1 dead
// once phase-1 fragments consumed (enforced by __syncthreads).
#define OFF_B1   0        // 8704  We [64][136]
#define OFF_A1   8704
#define OFF_A2   8704     // 16896 raw [128][132]
#define OFF_P    25600    // 8192  fp32 edge tile staging
#define OFF_QS   33792    // 128 floats
#define OFF_BES  33920    // 128 floats
#define SMEM_U32 34048    // 136192 bytes

// ---------------------------------------------------------------------------
// Kernel P: We -> tf32(rna), padded layout
// ---------------------------------------------------------------------------
__global__ void prep_kernel(const float* __restrict__ We) {
    int t = blockIdx.x * 256 + threadIdx.x;   // 0..8191
    if (t < 64 * 128) {
        int k = t >> 7, c = t & 127;
        g_We1[k * 136 + c] = f2tf(We[k * CH + c]);
    }
}

// ---------------------------------------------------------------------------
// Kernel A: qkv = x @ Wqkv + bqkv  (exact fp32)
// ---------------------------------------------------------------------------
__global__ void __launch_bounds__(QKVW) qkv_kernel(
    const float* __restrict__ x, const float* __restrict__ W,
    const float* __restrict__ bias)
{
    __shared__ float xs[CH];
    int row = blockIdx.x, col = threadIdx.x;
    if (col < CH) xs[col] = x[row * CH + col];
    __syncthreads();
    float acc = bias[col];
#pragma unroll 16
    for (int k = 0; k < CH; k++) acc = fmaf(xs[k], W[k * QKVW + col], acc);
    g_QKV[row * QKVW + col] = acc;
}

// ---------------------------------------------------------------------------
// Kernel B: persistent fused edge pipeline, tf32 mma.
// Phase 2 computed transposed: edge_out^T = Weo^T x raw^T with Weo^T
// fragments held in registers across all tiles.
// ---------------------------------------------------------------------------
__global__ void __launch_bounds__(512) edge_mma_kernel(
    const float* __restrict__ edge_attr,
    const float* __restrict__ be, const float* __restrict__ beo,
    const float* __restrict__ Weo,
    float* __restrict__ edge_out)
{
    extern __shared__ uint32_t smu[];
    float* qs  = (float*)(smu + OFF_QS);
    float* bes = (float*)(smu + OFF_BES);
    const uint32_t p_sm = smem_u32(smu) + OFF_P * 4;

    const int t = threadIdx.x, lane = t & 31, w = t >> 5;
    const int g = lane >> 2, c4 = lane & 3;
    // phase 1 mapping: 4x4 warp grid over [128j x 128c]
    const int m0 = (w & 3) * 32, n0 = (w >> 2) * 32;
    // phase 2 mapping: 4(eo) x 4(j) warp grid over [64eo x 128j] transposed out
    const int eo0 = (w & 3) * 16, jn = (w >> 2) * 32;

    // ---- one-time: We tile to smem, bias, persistent Weo^T fragments ----
    for (int i = t; i < 64 * 136; i += 512) smu[OFF_B1 + i] = g_We1[i];
    if (t < CH) bes[t] = be[t];

    const float beo0 = beo[eo0 + g], beo1 = beo[eo0 + g + 8];

    uint32_t areg[16][4];
#pragma unroll
    for (int ks = 0; ks < 16; ks++) {
        int k0 = ks * 8 + c4;
        areg[ks][0] = f2tf(Weo[k0 * EH + eo0 + g]);
        areg[ks][1] = f2tf(Weo[k0 * EH + eo0 + g + 8]);
        areg[ks][2] = f2tf(Weo[(k0 + 4) * EH + eo0 + g]);
        areg[ks][3] = f2tf(Weo[(k0 + 4) * EH + eo0 + g + 8]);
    }

    // ---- prefetch first tile ----
    int tile = blockIdx.x;
    if (tile < NT) {
        int bi = tile >> 2, jt = tile & 3;
        const float4* src = (const float4*)(edge_attr + ((size_t)bi * NN + jt * TJM) * EH);
#pragma unroll
        for (int s = 0; s < 4; s++) {
            int fi = t + s * 512;
            cp16(p_sm + fi * 16, src + fi);
        }
    }
    CP_COMMIT();

    for (; tile < NT; tile += EGRID) {
        const int bi = tile >> 2, jt = tile & 3;
        const int b = bi >> 9, jbase = jt * TJM;

        CP_WAIT0();
        __syncthreads();       // staging valid; prior tile's A2 reads done

        // ---- copy staged tile -> A1 (rna-tf32), vectorized; q row ----
        {
            const float4* Pf4 = (const float4*)(smu + OFF_P);
#pragma unroll
            for (int s = 0; s < 4; s++) {
                int fi = t + s * 512;              // 2048 float4
                int row = fi >> 4, q4 = fi & 15;
                float4 v = Pf4[fi];
                *(uint4*)(smu + OFF_A1 + row * 68 + q4 * 4) =
                    make_uint4(f2tf(v.x), f2tf(v.y), f2tf(v.z), f2tf(v.w));
            }
            if (t < CH) qs[t] = g_QKV[bi * QKVW + t];
        }
        __syncthreads();       // A1/qs ready; staging consumed

        // ---- prefetch next tile ----
        {
            int nt2 = tile + EGRID;
            if (nt2 < NT) {
                int nbi = nt2 >> 2, njt = nt2 & 3;
                const float4* src = (const float4*)(edge_attr + ((size_t)nbi * NN + njt * TJM) * EH);
#pragma unroll
                for (int s = 0; s < 4; s++) {
                    int fi = t + s * 512;
                    cp16(p_sm + fi * 16, src + fi);
                }
            }
            CP_COMMIT();
        }

        // ---- phase 1: e[128,128] = A1[128,64] x We, 8 tf32 k-steps ----
        float acc[2][4][4];
#pragma unroll
        for (int mf = 0; mf < 2; mf++)
#pragma unroll
            for (int nf = 0; nf < 4; nf++)
#pragma unroll
                for (int i = 0; i < 4; i++) acc[mf][nf][i] = 0.f;

#pragma unroll
        for (int ks = 0; ks < 8; ks++) {
            const int kb = ks * 8;
            uint32_t a[2][4];
#pragma unroll
            for (int mf = 0; mf < 2; mf++) {
                int r0 = OFF_A1 + (m0 + mf * 16 + g) * 68 + kb + c4;
                int r1 = r0 + 8 * 68;
                a[mf][0] = smu[r0];     a[mf][1] = smu[r1];
                a[mf][2] = smu[r0 + 4]; a[mf][3] = smu[r1 + 4];
            }
#pragma unroll
            for (int nf = 0; nf < 4; nf++) {
                int bidx = OFF_B1 + (kb + c4) * 136 + n0 + nf * 8 + g;
                uint32_t b0 = smu[bidx], b1 = smu[bidx + 4 * 136];
#pragma unroll
                for (int mf = 0; mf < 2; mf++)
                    mma_tf32(acc[mf][nf], a[mf][0], a[mf][1], a[mf][2], a[mf][3], b0, b1);
            }
        }

        // ---- epilogue 1: raw = (e+be)*q*k, logits ----
#pragma unroll
        for (int mf = 0; mf < 2; mf++) {
#pragma unroll
            for (int cih = 0; cih < 2; cih++) {
                int r = m0 + mf * 16 + g + cih * 8;
                const float* kr = g_QKV + ((size_t)(b * NN + jbase + r)) * QKVW + CH;
                float lg0 = 0.f, lg1 = 0.f;
#pragma unroll
                for (int nf = 0; nf < 4; nf++) {
                    int c = n0 + nf * 8 + 2 * c4;
                    float2 kk = *(const float2*)(kr + c);
                    float2 qq = *(const float2*)(qs + c);
                    float2 bb = *(const float2*)(bes + c);
                    float r0 = (acc[mf][nf][cih * 2 + 0] + bb.x) * qq.x * kk.x;
                    float r1 = (acc[mf][nf][cih * 2 + 1] + bb.y) * qq.y * kk.y;
                    acc[mf][nf][cih * 2 + 0] = r0;
                    acc[mf][nf][cih * 2 + 1] = r1;
                    float p = r0 + r1;
                    if (nf < 2) lg0 += p; else lg1 += p;
                }
                lg0 += __shfl_xor_sync(0xffffffffu, lg0, 1);
                lg0 += __shfl_xor_sync(0xffffffffu, lg0, 2);
                lg1 += __shfl_xor_sync(0xffffffffu, lg1, 1);
                lg1 += __shfl_xor_sync(0xffffffffu, lg1, 2);
                if (c4 == 0) {
                    *(float2*)(g_LOG + ((size_t)bi * NN + jbase + r) * NH + 2 * (w >> 2)) =
                        make_float2(lg0 * 0.25f, lg1 * 0.25f);
                }
            }
        }
        __syncthreads();   // phase-1 A1 reads done before A2 overlay write

        // ---- store raw as rna-tf32 into A2 [128][132] ----
#pragma unroll
        for (int mf = 0; mf < 2; mf++)
#pragma unroll
            for (int cih = 0; cih < 2; cih++) {
                int r = m0 + mf * 16 + g + cih * 8;
#pragma unroll
                for (int nf = 0; nf < 4; nf++) {
                    int c = n0 + nf * 8 + 2 * c4;
                    *(uint2*)(smu + OFF_A2 + r * 132 + c) =
                        make_uint2(f2tf(acc[mf][nf][cih * 2 + 0]),
                                   f2tf(acc[mf][nf][cih * 2 + 1]));
                }
            }
        __syncthreads();

        // ---- phase 2 (transposed): out^T[64,128] = Weo^T x raw^T ----
        // A = areg (persistent), B = raw^T read from A2's natural layout.
        float o[4][4];
#pragma unroll
        for (int nf = 0; nf < 4; nf++)
#pragma unroll
            for (int i = 0; i < 4; i++) o[nf][i] = 0.f;

#pragma unroll
        for (int ks = 0; ks < 16; ks++) {
            const int kb = ks * 8;
#pragma unroll
            for (int nf = 0; nf < 4; nf++) {
                int bidx = OFF_A2 + (jn + nf * 8 + g) * 132 + kb + c4;
                uint32_t b0 = smu[bidx], b1 = smu[bidx + 4];
                mma_tf32(o[nf], areg[ks][0], areg[ks][1], areg[ks][2], areg[ks][3], b0, b1);
            }
        }

        // ---- epilogue 2: + beo, scatter-store (out is transposed) ----
#pragma unroll
        for (int nf = 0; nf < 4; nf++) {
            int j = jn + nf * 8 + 2 * c4;
            float* d0 = edge_out + ((size_t)bi * NN + jbase + j) * EH + eo0 + g;
            float* d1 = d0 + EH;      // j+1
            d0[0] = o[nf][0] + beo0;
            d1[0] = o[nf][1] + beo0;
            d0[8] = o[nf][2] + beo1;
            d1[8] = o[nf][3] + beo1;
        }
    }
}

// ---------------------------------------------------------------------------
// Kernel C: masked softmax over j, node = att @ v, node_out = node @ Wno + bno
// 512 threads: 2 warps per head softmax, 4-way splits elsewhere.
// ---------------------------------------------------------------------------
__global__ void __launch_bounds__(512) softmax_node_kernel(
    const int* __restrict__ mask,
    const float* __restrict__ Wno, const float* __restrict__ bno,
    float* __restrict__ node_out)
{
    __shared__ float ls[NN * 9];      // stride 9: conflict-free column walks
    __shared__ float partial[4][CH];
    __shared__ float np[4][CH];
    __shared__ float redm[2][NH], reds[2][NH];
    __shared__ float node_s[CH];
    __shared__ float invs[NH];
    __shared__ int msk[NN];

    int bi = blockIdx.x, b = bi >> 9, t = threadIdx.x;

    if (t < NN) msk[t] = mask[b * NN + t];
    __syncthreads();

    const float4* Lp = (const float4*)(g_LOG + (size_t)bi * NN * NH);
#pragma unroll
    for (int s = 0; s < 2; s++) {
        int fi = t + s * 512;
        float4 v = Lp[fi];
        int j = fi >> 1, hb = (fi & 1) * 4;
        if (!msk[j]) { v.x = v.y = v.z = v.w = -FLT_MAX; }
        ls[j * 9 + hb + 0] = v.x;
        ls[j * 9 + hb + 1] = v.y;
        ls[j * 9 + hb + 2] = v.z;
        ls[j * 9 + hb + 3] = v.w;
    }
    __syncthreads();

    {   // softmax: 2 warps per head (warp w: head w&7, j-half w>>3)
        int wH = (t >> 5) & 7, half = t >> 8, l = t & 31;
        int jb = half * 256 + l;
        float m = -FLT_MAX;
#pragma unroll
        for (int k = 0; k < 8; k++)
            m = fmaxf(m, ls[(jb + 32 * k) * 9 + wH]);
#pragma unroll
        for (int off = 16; off; off >>= 1)
            m = fmaxf(m, __shfl_xor_sync(0xffffffffu, m, off));
        if (l == 0) redm[half][wH] = m;
        __syncthreads();
        m = fmaxf(redm[0][wH], redm[1][wH]);
        float s = 0.f;
#pragma unroll
        for (int k = 0; k < 8; k++) {
            int j = jb + 32 * k;
            float p = __expf(ls[j * 9 + wH] - m);
            ls[j * 9 + wH] = p;
            s += p;
        }
#pragma unroll
        for (int off = 16; off; off >>= 1)
            s += __shfl_xor_sync(0xffffffffu, s, off);
        if (l == 0) reds[half][wH] = s;
        __syncthreads();
        if (t < NH) invs[t] = 1.f / (reds[0][t] + reds[1][t]);
    }

    {   // attention * V, 4-way j split
        int q = t >> 7, c = t & 127, h = c >> 4;
        const float* Vp = g_QKV + (size_t)(b * NN + q * 128) * QKVW + 2 * CH + c;
        const float* lsp = ls + (q * 128) * 9 + h;
        float a0 = 0.f, a1 = 0.f;
#pragma unroll 4
        for (int j = 0; j < 128; j += 2) {
            a0 = fmaf(lsp[j * 9],       Vp[(size_t)j * QKVW],       a0);
            a1 = fmaf(lsp[(j + 1) * 9], Vp[(size_t)(j + 1) * QKVW], a1);
        }
        partial[q][c] = a0 + a1;
    }
    __syncthreads();

    if (t < CH)
        node_s[t] = (partial[0][t] + partial[1][t] + partial[2][t] + partial[3][t])
                    * invs[t >> 4];
    __syncthreads();

    {   // node @ Wno, 4-way k split
        int q = t >> 7, c = t & 127;
        float o = 0.f;
#pragma unroll 8
        for (int k = 0; k < 32; k++)
            o = fmaf(node_s[q * 32 + k], Wno[(q * 32 + k) * CH + c], o);
        np[q][c] = o;
    }
    __syncthreads();

    if (t < CH)
        node_out[bi * CH + t] = np[0][t] + np[1][t] + np[2][t] + np[3][t] + bno[t];
}

// ---------------------------------------------------------------------------
extern "C" void kernel_launch(void* const* d_in, const int* in_sizes, int n_in,
                              void* d_out, int out_size)
{
    const float* x         = (const float*)d_in[0];
    const float* edge_attr = (const float*)d_in[1];
    const int*   mask      = (const int*)d_in[2];
    const float* Wqkv      = (const float*)d_in[3];
    const float* bqkv      = (const float*)d_in[4];
    const float* We        = (const float*)d_in[5];
    const float* be        = (const float*)d_in[6];
    const float* Wno       = (const float*)d_in[7];
    const float* bno       = (const float*)d_in[8];
    const float* Weo       = (const float*)d_in[9];
    const float* beo       = (const float*)d_in[10];

    float* out      = (float*)d_out;
    float* node_out = out;                       // (2,512,128)
    float* edge_out = out + NB * NN * CH;        // (2,512,512,64)

    prep_kernel<<<32, 256>>>(We);
    qkv_kernel<<<NB * NN, QKVW>>>(x, Wqkv, bqkv);

    size_t shmem = SMEM_U32 * sizeof(uint32_t);  // 136192 B
    cudaFuncSetAttribute(edge_mma_kernel,
                         cudaFuncAttributeMaxDynamicSharedMemorySize, (int)shmem);
    edge_mma_kernel<<<EGRID, 512, shmem>>>(edge_attr, be, beo, Weo, edge_out);

    softmax_node_kernel<<<NB * NN, 512>>>(mask, Wno, bno, node_out);
}

// round 11
// speedup vs baseline: 3.3384x; 1.2597x over previous
#include <cuda_runtime.h>
#include <cuda_fp16.h>
#include <cstdint>
#include <float.h>

#define NB 2
#define NN 512
#define NH 8
#define CH 128      // n_head * head_hidden
#define EH 64       // edge hidden
#define QKVW 384
#define TJM 128     // j-rows per tile (MMA M)
#define NT (NB * NN * 4)   // 4096 tiles
#define EGRID 148

// Scratch (device globals)
__device__ float g_QKV[NB * NN * QKVW];              // q|k|v per node row
__device__ float g_LOG[(size_t)NB * NN * NN * NH];   // attention logits
__device__ uint32_t g_WeP[32 * 136];                 // We fp16x2 [k2=32][c=128] stride 136

// ---------------------------------------------------------------------------
// helpers
// ---------------------------------------------------------------------------
__device__ __forceinline__ uint32_t pack_f16x2(float lo, float hi) {
    uint32_t d;
    asm("cvt.rn.f16x2.f32 %0, %1, %2;" : "=r"(d) : "f"(hi), "f"(lo));
    return d;
}

__device__ __forceinline__ void mma_f16(float* c,
    uint32_t a0, uint32_t a1, uint32_t a2, uint32_t a3,
    uint32_t b0, uint32_t b1)
{
    asm volatile(
        "mma.sync.aligned.m16n8k16.row.col.f32.f16.f16.f32 "
        "{%0,%1,%2,%3}, {%4,%5,%6,%7}, {%8,%9}, {%0,%1,%2,%3};"
        : "+f"(c[0]), "+f"(c[1]), "+f"(c[2]), "+f"(c[3])
        : "r"(a0), "r"(a1), "r"(a2), "r"(a3), "r"(b0), "r"(b1));
}

__device__ __forceinline__ uint32_t smem_u32(const void* p) {
    uint32_t a;
    asm("{ .reg .u64 t; cvta.to.shared.u64 t, %1; cvt.u32.u64 %0, t; }"
        : "=r"(a) : "l"(p));
    return a;
}
__device__ __forceinline__ void cp16(uint32_t smaddr, const void* g) {
    asm volatile("cp.async.cg.shared.global [%0], [%1], 16;"
                 :: "r"(smaddr), "l"(g) : "memory");
}
#define CP_COMMIT() asm volatile("cp.async.commit_group;" ::: "memory")
#define CP_WAIT0()  asm volatile("cp.async.wait_group 0;" ::: "memory")

// SMEM map (u32 units). A1 (f16x2 edge tile [128][36]) overlays A2
// (f16x2 raw [128][68]) — A1 dead once phase-1 fragments consumed.
#define OFF_B1   0        // 4352  We fp16x2 [32][136]
#define OFF_A1   4352
#define OFF_A2   4352     // 8704  raw fp16x2 [128][68]
#define OFF_P    13056    // 8192  fp32 edge tile staging
#define OFF_QS   21248    // 128 floats
#define OFF_BES  21376    // 128 floats
#define SMEM_U32 21504    // 86016 bytes

// ---------------------------------------------------------------------------
// Kernel P: We -> packed fp16x2 along k
// ---------------------------------------------------------------------------
__global__ void prep_kernel(const float* __restrict__ We) {
    int t = blockIdx.x * 256 + threadIdx.x;   // 0..4095
    if (t < 32 * 128) {
        int k2 = t >> 7, c = t & 127;
        g_WeP[k2 * 136 + c] = pack_f16x2(We[(2 * k2) * CH + c], We[(2 * k2 + 1) * CH + c]);
    }
}

// ---------------------------------------------------------------------------
// Kernel A: qkv = x @ Wqkv + bqkv.  128 blocks x 384 threads, 8 rows/block.
// ---------------------------------------------------------------------------
__global__ void __launch_bounds__(QKVW) qkv_kernel(
    const float* __restrict__ x, const float* __restrict__ W,
    const float* __restrict__ bias)
{
    __shared__ float xs[8 * CH];
    const int t = threadIdx.x;
    const int r0 = blockIdx.x * 8;

    for (int i = t; i < 8 * CH; i += QKVW) xs[i] = x[r0 * CH + i];
    float bcol = bias[t];
    __syncthreads();

    float acc[8];
#pragma unroll
    for (int r = 0; r < 8; r++) acc[r] = bcol;

#pragma unroll 4
    for (int k = 0; k < CH; k += 4) {
        float w0 = __ldg(W + (k + 0) * QKVW + t);
        float w1 = __ldg(W + (k + 1) * QKVW + t);
        float w2 = __ldg(W + (k + 2) * QKVW + t);
        float w3 = __ldg(W + (k + 3) * QKVW + t);
#pragma unroll
        for (int r = 0; r < 8; r++) {
            float4 xv = *(const float4*)(xs + r * CH + k);
            acc[r] = fmaf(xv.x, w0, acc[r]);
            acc[r] = fmaf(xv.y, w1, acc[r]);
            acc[r] = fmaf(xv.z, w2, acc[r]);
            acc[r] = fmaf(xv.w, w3, acc[r]);
        }
    }
#pragma unroll
    for (int r = 0; r < 8; r++) g_QKV[(r0 + r) * QKVW + t] = acc[r];
}

// ---------------------------------------------------------------------------
// Kernel B: persistent fused edge pipeline, fp16 mma (fp32 accum).
// Phase 2 transposed: edge_out^T = Weo^T x raw^T, Weo^T fragments persistent.
// ---------------------------------------------------------------------------
__global__ void __launch_bounds__(512) edge_mma_kernel(
    const float* __restrict__ edge_attr,
    const float* __restrict__ be, const float* __restrict__ beo,
    const float* __restrict__ Weo,
    float* __restrict__ edge_out)
{
    extern __shared__ uint32_t smu[];
    float* qs  = (float*)(smu + OFF_QS);
    float* bes = (float*)(smu + OFF_BES);
    const uint32_t p_sm = smem_u32(smu) + OFF_P * 4;

    const int t = threadIdx.x, lane = t & 31, w = t >> 5;
    const int g = lane >> 2, c4 = lane & 3;
    // phase 1 mapping: 4x4 warp grid over [128j x 128c]
    const int m0 = (w & 3) * 32, n0 = (w >> 2) * 32;
    const int n0h = n0 >> 1;                    // u32 col base in A2
    // phase 2 mapping: 4(eo) x 4(j) warp grid over [64eo x 128j]
    const int eo0 = (w & 3) * 16, jn = (w >> 2) * 32;

    // ---- one-time: We tile to smem, bias, persistent Weo^T fp16 fragments ----
    for (int i = t; i < 32 * 136; i += 512) smu[OFF_B1 + i] = g_WeP[i];
    if (t < CH) bes[t] = be[t];

    const float beo0 = beo[eo0 + g], beo1 = beo[eo0 + g + 8];

    uint32_t areg[8][4];                        // Weo^T [64eo][128k] fragments
#pragma unroll
    for (int ks = 0; ks < 8; ks++) {
        int k2a = ks * 8 + c4;                  // packed-k index (pairs)
        int k2b = k2a + 4;
        areg[ks][0] = pack_f16x2(__ldg(Weo + (2 * k2a)     * EH + eo0 + g),
                                 __ldg(Weo + (2 * k2a + 1) * EH + eo0 + g));
        areg[ks][1] = pack_f16x2(__ldg(Weo + (2 * k2a)     * EH + eo0 + g + 8),
                                 __ldg(Weo + (2 * k2a + 1) * EH + eo0 + g + 8));
        areg[ks][2] = pack_f16x2(__ldg(Weo + (2 * k2b)     * EH + eo0 + g),
                                 __ldg(Weo + (2 * k2b + 1) * EH + eo0 + g));
        areg[ks][3] = pack_f16x2(__ldg(Weo + (2 * k2b)     * EH + eo0 + g + 8),
                                 __ldg(Weo + (2 * k2b + 1) * EH + eo0 + g + 8));
    }

    // ---- prefetch first tile ----
    int tile = blockIdx.x;
    if (tile < NT) {
        int bi = tile >> 2, jt = tile & 3;
        const float4* src = (const float4*)(edge_attr + ((size_t)bi * NN + jt * TJM) * EH);
#pragma unroll
        for (int s = 0; s < 4; s++) {
            int fi = t + s * 512;
            cp16(p_sm + fi * 16, src + fi);
        }
    }
    CP_COMMIT();

    for (; tile < NT; tile += EGRID) {
        const int bi = tile >> 2, jt = tile & 3;
        const int b = bi >> 9, jbase = jt * TJM;

        CP_WAIT0();
        __syncthreads();       // staging valid; prior tile's A2 reads done

        // ---- staged fp32 tile -> A1 fp16x2 [128][36]; q row ----
        {
            const float4* Pf4 = (const float4*)(smu + OFF_P);
#pragma unroll
            for (int s = 0; s < 4; s++) {
                int fi = t + s * 512;              // 2048 float4
                int row = fi >> 4, q4 = fi & 15;
                float4 v = Pf4[fi];
                *(uint2*)(smu + OFF_A1 + row * 36 + q4 * 2) =
                    make_uint2(pack_f16x2(v.x, v.y), pack_f16x2(v.z, v.w));
            }
            if (t < CH) qs[t] = g_QKV[bi * QKVW + t];
        }
        __syncthreads();       // A1/qs ready; staging consumed

        // ---- prefetch next tile ----
        {
            int nt2 = tile + EGRID;
            if (nt2 < NT) {
                int nbi = nt2 >> 2, njt = nt2 & 3;
                const float4* src = (const float4*)(edge_attr + ((size_t)nbi * NN + njt * TJM) * EH);
#pragma unroll
                for (int s = 0; s < 4; s++) {
                    int fi = t + s * 512;
                    cp16(p_sm + fi * 16, src + fi);
                }
            }
            CP_COMMIT();
        }

        // ---- phase 1: e[128,128] = A1[128,64] x We, 4 fp16 k16-steps ----
        float acc[2][4][4];
#pragma unroll
        for (int mf = 0; mf < 2; mf++)
#pragma unroll
            for (int nf = 0; nf < 4; nf++)
#pragma unroll
                for (int i = 0; i < 4; i++) acc[mf][nf][i] = 0.f;

#pragma unroll
        for (int ks = 0; ks < 4; ks++) {
            const int kb = ks * 8;                   // u32 offset (8 u32 = 16 k)
            uint32_t a[2][4];
#pragma unroll
            for (int mf = 0; mf < 2; mf++) {
                int r0 = OFF_A1 + (m0 + mf * 16 + g) * 36 + kb + c4;
                int r1 = r0 + 8 * 36;
                a[mf][0] = smu[r0];     a[mf][1] = smu[r1];
                a[mf][2] = smu[r0 + 4]; a[mf][3] = smu[r1 + 4];
            }
#pragma unroll
            for (int nf = 0; nf < 4; nf++) {
                int bidx = OFF_B1 + (kb + c4) * 136 + n0 + nf * 8 + g;
                uint32_t b0 = smu[bidx], b1 = smu[bidx + 4 * 136];
#pragma unroll
                for (int mf = 0; mf < 2; mf++)
                    mma_f16(acc[mf][nf], a[mf][0], a[mf][1], a[mf][2], a[mf][3], b0, b1);
            }
        }

        // ---- epilogue 1: raw = (e+be)*q*k, logits ----
#pragma unroll
        for (int mf = 0; mf < 2; mf++) {
#pragma unroll
            for (int cih = 0; cih < 2; cih++) {
                int r = m0 + mf * 16 + g + cih * 8;
                const float* kr = g_QKV + ((size_t)(b * NN + jbase + r)) * QKVW + CH;
                float lg0 = 0.f, lg1 = 0.f;
#pragma unroll
                for (int nf = 0; nf < 4; nf++) {
                    int c = n0 + nf * 8 + 2 * c4;
                    float2 kk = *(const float2*)(kr + c);
                    float2 qq = *(const float2*)(qs + c);
                    float2 bb = *(const float2*)(bes + c);
                    float r0 = (acc[mf][nf][cih * 2 + 0] + bb.x) * qq.x * kk.x;
                    float r1 = (acc[mf][nf][cih * 2 + 1] + bb.y) * qq.y * kk.y;
                    acc[mf][nf][cih * 2 + 0] = r0;
                    acc[mf][nf][cih * 2 + 1] = r1;
                    float p = r0 + r1;
                    if (nf < 2) lg0 += p; else lg1 += p;
                }
                lg0 += __shfl_xor_sync(0xffffffffu, lg0, 1);
                lg0 += __shfl_xor_sync(0xffffffffu, lg0, 2);
                lg1 += __shfl_xor_sync(0xffffffffu, lg1, 1);
                lg1 += __shfl_xor_sync(0xffffffffu, lg1, 2);
                if (c4 == 0) {
                    *(float2*)(g_LOG + ((size_t)bi * NN + jbase + r) * NH + 2 * (w >> 2)) =
                        make_float2(lg0 * 0.25f, lg1 * 0.25f);
                }
            }
        }
        __syncthreads();   // phase-1 A1 reads done before A2 overlay write

        // ---- store raw as fp16x2 into A2 [128][68] ----
#pragma unroll
        for (int mf = 0; mf < 2; mf++)
#pragma unroll
            for (int cih = 0; cih < 2; cih++) {
                int r = m0 + mf * 16 + g + cih * 8;
#pragma unroll
                for (int nf = 0; nf < 4; nf++) {
                    smu[OFF_A2 + r * 68 + n0h + nf * 4 + c4] =
                        pack_f16x2(acc[mf][nf][cih * 2 + 0], acc[mf][nf][cih * 2 + 1]);
                }
            }
        __syncthreads();

        // ---- phase 2 (transposed): out^T[64,128] = Weo^T x raw^T, 8 steps ----
        float o[4][4];
#pragma unroll
        for (int nf = 0; nf < 4; nf++)
#pragma unroll
            for (int i = 0; i < 4; i++) o[nf][i] = 0.f;

#pragma unroll
        for (int ks = 0; ks < 8; ks++) {
            const int kb = ks * 8;
#pragma unroll
            for (int nf = 0; nf < 4; nf++) {
                int bidx = OFF_A2 + (jn + nf * 8 + g) * 68 + kb + c4;
                uint32_t b0 = smu[bidx], b1 = smu[bidx + 4];
                mma_f16(o[nf], areg[ks][0], areg[ks][1], areg[ks][2], areg[ks][3], b0, b1);
            }
        }

        // ---- epilogue 2: + beo, scatter-store (out is transposed) ----
#pragma unroll
        for (int nf = 0; nf < 4; nf++) {
            int j = jn + nf * 8 + 2 * c4;
            float* d0 = edge_out + ((size_t)bi * NN + jbase + j) * EH + eo0 + g;
            float* d1 = d0 + EH;      // j+1
            d0[0] = o[nf][0] + beo0;
            d1[0] = o[nf][1] + beo0;
            d0[8] = o[nf][2] + beo1;
            d1[8] = o[nf][3] + beo1;
        }
    }
}

// ---------------------------------------------------------------------------
// Kernel C: masked softmax over j, node = att @ v, node_out = node @ Wno + bno
// 512 threads; vectorized float4 att*V and Wno.
// ---------------------------------------------------------------------------
__global__ void __launch_bounds__(512) softmax_node_kernel(
    const int* __restrict__ mask,
    const float* __restrict__ Wno, const float* __restrict__ bno,
    float* __restrict__ node_out)
{
    __shared__ float ls[NN * 9];        // stride 9: conflict-free column walks
    __shared__ float partial[16 * 132];
    __shared__ float np[16 * 132];
    __shared__ float redm[2][NH], reds[2][NH];
    __shared__ float node_s[CH];
    __shared__ float invs[NH];
    __shared__ int msk[NN];

    int bi = blockIdx.x, b = bi >> 9, t = threadIdx.x;

    if (t < NN) msk[t] = mask[b * NN + t];
    __syncthreads();

    const float4* Lp = (const float4*)(g_LOG + (size_t)bi * NN * NH);
#pragma unroll
    for (int s = 0; s < 2; s++) {
        int fi = t + s * 512;
        float4 v = Lp[fi];
        int j = fi >> 1, hb = (fi & 1) * 4;
        if (!msk[j]) { v.x = v.y = v.z = v.w = -FLT_MAX; }
        ls[j * 9 + hb + 0] = v.x;
        ls[j * 9 + hb + 1] = v.y;
        ls[j * 9 + hb + 2] = v.z;
        ls[j * 9 + hb + 3] = v.w;
    }
    __syncthreads();

    {   // softmax: 2 warps per head (warp w: head w&7, j-half w>>3)
        int wH = (t >> 5) & 7, half = t >> 8, l = t & 31;
        int jb = half * 256 + l;
        float m = -FLT_MAX;
#pragma unroll
        for (int k = 0; k < 8; k++)
            m = fmaxf(m, ls[(jb + 32 * k) * 9 + wH]);
#pragma unroll
        for (int off = 16; off; off >>= 1)
            m = fmaxf(m, __shfl_xor_sync(0xffffffffu, m, off));
        if (l == 0) redm[half][wH] = m;
        __syncthreads();
        m = fmaxf(redm[0][wH], redm[1][wH]);
        float s = 0.f;
#pragma unroll
        for (int k = 0; k < 8; k++) {
            int j = jb + 32 * k;
            float p = __expf(ls[j * 9 + wH] - m);
            ls[j * 9 + wH] = p;
            s += p;
        }
#pragma unroll
        for (int off = 16; off; off >>= 1)
            s += __shfl_xor_sync(0xffffffffu, s, off);
        if (l == 0) reds[half][wH] = s;
        __syncthreads();
        if (t < NH) invs[t] = 1.f / (reds[0][t] + reds[1][t]);
    }

    {   // attention * V: warp wq owns 32 j-rows; lane l -> channels 4l..4l+3
        int wq = t >> 5, l = t & 31, h = l >> 2;
        const float4* Vp = (const float4*)(g_QKV + (size_t)(b * NN + wq * 32) * QKVW + 2 * CH);
        const float* lsp = ls + (wq * 32) * 9 + h;
        float4 a = make_float4(0.f, 0.f, 0.f, 0.f);
#pragma unroll 8
        for (int j = 0; j < 32; j++) {
            float p = lsp[j * 9];
            float4 v = __ldg(Vp + (size_t)j * (QKVW / 4) + l);
            a.x = fmaf(p, v.x, a.x);
            a.y = fmaf(p, v.y, a.y);
            a.z = fmaf(p, v.z, a.z);
            a.w = fmaf(p, v.w, a.w);
        }
        *(float4*)(partial + wq * 132 + 4 * l) = a;
    }
    __syncthreads();

    if (t < CH) {
        float s = 0.f;
#pragma unroll
        for (int p = 0; p < 16; p++) s += partial[p * 132 + t];
        node_s[t] = s * invs[t >> 4];
    }
    __syncthreads();

    {   // node @ Wno: warp ws owns k-slice ws*8..+8; lane -> cols 4l..4l+3
        int ws = t >> 5, l = t & 31;
        float4 o = make_float4(0.f, 0.f, 0.f, 0.f);
#pragma unroll
        for (int k = 0; k < 8; k++) {
            float s = node_s[ws * 8 + k];
            float4 wv = __ldg((const float4*)(Wno + (ws * 8 + k) * CH) + l);
            o.x = fmaf(s, wv.x, o.x);
            o.y = fmaf(s, wv.y, o.y);
            o.z = fmaf(s, wv.z, o.z);
            o.w = fmaf(s, wv.w, o.w);
        }
        *(float4*)(np + ws * 132 + 4 * l) = o;
    }
    __syncthreads();

    if (t < CH) {
        float r = bno[t];
#pragma unroll
        for (int p = 0; p < 16; p++) r += np[p * 132 + t];
        node_out[bi * CH + t] = r;
    }
}

// ---------------------------------------------------------------------------
extern "C" void kernel_launch(void* const* d_in, const int* in_sizes, int n_in,
                              void* d_out, int out_size)
{
    const float* x         = (const float*)d_in[0];
    const float* edge_attr = (const float*)d_in[1];
    const int*   mask      = (const int*)d_in[2];
    const float* Wqkv      = (const float*)d_in[3];
    const float* bqkv      = (const float*)d_in[4];
    const float* We        = (const float*)d_in[5];
    const float* be        = (const float*)d_in[6];
    const float* Wno       = (const float*)d_in[7];
    const float* bno       = (const float*)d_in[8];
    const float* Weo       = (const float*)d_in[9];
    const float* beo       = (const float*)d_in[10];

    float* out      = (float*)d_out;
    float* node_out = out;                       // (2,512,128)
    float* edge_out = out + NB * NN * CH;        // (2,512,512,64)

    prep_kernel<<<16, 256>>>(We);
    qkv_kernel<<<128, QKVW>>>(x, Wqkv, bqkv);

    size_t shmem = SMEM_U32 * sizeof(uint32_t);  // 86016 B
    cudaFuncSetAttribute(edge_mma_kernel,
                         cudaFuncAttributeMaxDynamicSharedMemorySize, (int)shmem);
    edge_mma_kernel<<<EGRID, 512, shmem>>>(edge_attr, be, beo, Weo, edge_out);

    softmax_node_kernel<<<NB * NN, 512>>>(mask, Wno, bno, node_out);
}

// round 12
// speedup vs baseline: 3.5971x; 1.0775x over previous
#include <cuda_runtime.h>
#include <cuda_fp16.h>
#include <cstdint>
#include <float.h>

#define NB 2
#define NN 512
#define NH 8
#define CH 128      // n_head * head_hidden
#define EH 64       // edge hidden
#define QKVW 384
#define TJM 128     // j-rows per tile (MMA M)
#define NT (NB * NN * 4)   // 4096 tiles
#define EGRID 148

// Scratch (device globals)
__device__ float g_QKV[NB * NN * QKVW];              // q|k|v per node row
__device__ float g_LOG[(size_t)NB * NN * NN * NH];   // attention logits
__device__ uint32_t g_WeP[32 * 136];                 // We fp16x2 [k2=32][c=128] stride 136

// ---------------------------------------------------------------------------
// helpers
// ---------------------------------------------------------------------------
__device__ __forceinline__ uint32_t pack_f16x2(float lo, float hi) {
    uint32_t d;
    asm("cvt.rn.f16x2.f32 %0, %1, %2;" : "=r"(d) : "f"(hi), "f"(lo));
    return d;
}

__device__ __forceinline__ void mma_f16(float* c,
    uint32_t a0, uint32_t a1, uint32_t a2, uint32_t a3,
    uint32_t b0, uint32_t b1)
{
    asm volatile(
        "mma.sync.aligned.m16n8k16.row.col.f32.f16.f16.f32 "
        "{%0,%1,%2,%3}, {%4,%5,%6,%7}, {%8,%9}, {%0,%1,%2,%3};"
        : "+f"(c[0]), "+f"(c[1]), "+f"(c[2]), "+f"(c[3])
        : "r"(a0), "r"(a1), "r"(a2), "r"(a3), "r"(b0), "r"(b1));
}

__device__ __forceinline__ uint32_t smem_u32(const void* p) {
    uint32_t a;
    asm("{ .reg .u64 t; cvta.to.shared.u64 t, %1; cvt.u32.u64 %0, t; }"
        : "=r"(a) : "l"(p));
    return a;
}
__device__ __forceinline__ void cp16(uint32_t smaddr, const void* g) {
    asm volatile("cp.async.cg.shared.global [%0], [%1], 16;"
                 :: "r"(smaddr), "l"(g) : "memory");
}
#define CP_COMMIT() asm volatile("cp.async.commit_group;" ::: "memory")
#define CP_WAIT0()  asm volatile("cp.async.wait_group 0;" ::: "memory")

// SMEM map (u32 units). A1 and A2 now DISJOINT (drops one barrier per tile).
// K tile staged in fp32, stride 136 (conflict-free for quarter-warp float2
// reads: bank = g*8 + 2*c4, disjoint within each 8-lane phase).
#define OFF_B1   0        // 4352   We fp16x2 [32][136]
#define OFF_A1   4352     // 4608   edge tile fp16x2 [128][36]
#define OFF_A2   8960     // 8704   raw fp16x2 [128][68]
#define OFF_P    17664    // 8192   fp32 edge tile staging
#define OFF_K    25856    // 17408  K tile fp32 [128][136]
#define OFF_QS   43264    // 128 floats
#define OFF_BES  43392    // 128 floats
#define SMEM_U32 43520    // 174080 bytes

// ---------------------------------------------------------------------------
// Kernel P: We -> packed fp16x2 along k
// ---------------------------------------------------------------------------
__global__ void prep_kernel(const float* __restrict__ We) {
    int t = blockIdx.x * 256 + threadIdx.x;   // 0..4095
    if (t < 32 * 128) {
        int k2 = t >> 7, c = t & 127;
        g_WeP[k2 * 136 + c] = pack_f16x2(We[(2 * k2) * CH + c], We[(2 * k2 + 1) * CH + c]);
    }
}

// ---------------------------------------------------------------------------
// Kernel A: qkv = x @ Wqkv + bqkv.  128 blocks x 384 threads, 8 rows/block.
// ---------------------------------------------------------------------------
__global__ void __launch_bounds__(QKVW) qkv_kernel(
    const float* __restrict__ x, const float* __restrict__ W,
    const float* __restrict__ bias)
{
    __shared__ float xs[8 * CH];
    const int t = threadIdx.x;
    const int r0 = blockIdx.x * 8;

    for (int i = t; i < 8 * CH; i += QKVW) xs[i] = x[r0 * CH + i];
    float bcol = bias[t];
    __syncthreads();

    float acc[8];
#pragma unroll
    for (int r = 0; r < 8; r++) acc[r] = bcol;

#pragma unroll 4
    for (int k = 0; k < CH; k += 4) {
        float w0 = __ldg(W + (k + 0) * QKVW + t);
        float w1 = __ldg(W + (k + 1) * QKVW + t);
        float w2 = __ldg(W + (k + 2) * QKVW + t);
        float w3 = __ldg(W + (k + 3) * QKVW + t);
#pragma unroll
        for (int r = 0; r < 8; r++) {
            float4 xv = *(const float4*)(xs + r * CH + k);
            acc[r] = fmaf(xv.x, w0, acc[r]);
            acc[r] = fmaf(xv.y, w1, acc[r]);
            acc[r] = fmaf(xv.z, w2, acc[r]);
            acc[r] = fmaf(xv.w, w3, acc[r]);
        }
    }
#pragma unroll
    for (int r = 0; r < 8; r++) g_QKV[(r0 + r) * QKVW + t] = acc[r];
}

// ---------------------------------------------------------------------------
// Kernel B: persistent fused edge pipeline, fp16 mma (fp32 accum).
// K tile staged to smem via cp.async (overlapping phase 2 of prior tile).
// ---------------------------------------------------------------------------
__global__ void __launch_bounds__(512) edge_mma_kernel(
    const float* __restrict__ edge_attr,
    const float* __restrict__ be, const float* __restrict__ beo,
    const float* __restrict__ Weo,
    float* __restrict__ edge_out)
{
    extern __shared__ uint32_t smu[];
    float* qs  = (float*)(smu + OFF_QS);
    float* bes = (float*)(smu + OFF_BES);
    float* ksm = (float*)(smu + OFF_K);
    const uint32_t sb = smem_u32(smu);
    const uint32_t p_sm = sb + OFF_P * 4;
    const uint32_t k_sm = sb + OFF_K * 4;

    const int t = threadIdx.x, lane = t & 31, w = t >> 5;
    const int g = lane >> 2, c4 = lane & 3;
    // phase 1 mapping: 4x4 warp grid over [128j x 128c]
    const int m0 = (w & 3) * 32, n0 = (w >> 2) * 32;
    const int n0h = n0 >> 1;                    // u32 col base in A2
    // phase 2 mapping: 4(eo) x 4(j) warp grid over [64eo x 128j]
    const int eo0 = (w & 3) * 16, jn = (w >> 2) * 32;

    // ---- one-time: We tile to smem, bias, persistent Weo^T fp16 fragments ----
    for (int i = t; i < 32 * 136; i += 512) smu[OFF_B1 + i] = g_WeP[i];
    if (t < CH) bes[t] = be[t];

    const float beo0 = beo[eo0 + g], beo1 = beo[eo0 + g + 8];

    uint32_t areg[8][4];                        // Weo^T [64eo][128k] fragments
#pragma unroll
    for (int ks = 0; ks < 8; ks++) {
        int k2a = ks * 8 + c4;                  // packed-k index (pairs)
        int k2b = k2a + 4;
        areg[ks][0] = pack_f16x2(__ldg(Weo + (2 * k2a)     * EH + eo0 + g),
                                 __ldg(Weo + (2 * k2a + 1) * EH + eo0 + g));
        areg[ks][1] = pack_f16x2(__ldg(Weo + (2 * k2a)     * EH + eo0 + g + 8),
                                 __ldg(Weo + (2 * k2a + 1) * EH + eo0 + g + 8));
        areg[ks][2] = pack_f16x2(__ldg(Weo + (2 * k2b)     * EH + eo0 + g),
                                 __ldg(Weo + (2 * k2b + 1) * EH + eo0 + g));
        areg[ks][3] = pack_f16x2(__ldg(Weo + (2 * k2b)     * EH + eo0 + g + 8),
                                 __ldg(Weo + (2 * k2b + 1) * EH + eo0 + g + 8));
    }

    // ---- prefetch first tile: edge + K ----
    int tile = blockIdx.x;
    if (tile < NT) {
        int bi = tile >> 2, jt = tile & 3, b0v = bi >> 9;
        const float4* src = (const float4*)(edge_attr + ((size_t)bi * NN + jt * TJM) * EH);
#pragma unroll
        for (int s = 0; s < 4; s++) {
            int fi = t + s * 512;
            cp16(p_sm + fi * 16, src + fi);
        }
        const float* kbase = g_QKV + ((size_t)(b0v * NN + jt * TJM)) * QKVW + CH;
#pragma unroll
        for (int s = 0; s < 8; s++) {
            int fi = t + s * 512;                 // 4096 float4
            int row = fi >> 5, cq = fi & 31;
            cp16(k_sm + (row * 136 + cq * 4) * 4, kbase + (size_t)row * QKVW + cq * 4);
        }
    }
    CP_COMMIT();

    for (; tile < NT; tile += EGRID) {
        const int bi = tile >> 2, jt = tile & 3;
        const int jbase = jt * TJM;

        CP_WAIT0();
        __syncthreads();       // staging P + K valid; prior tile done

        // ---- staged fp32 tile -> A1 fp16x2 [128][36]; q row ----
        {
            const float4* Pf4 = (const float4*)(smu + OFF_P);
#pragma unroll
            for (int s = 0; s < 4; s++) {
                int fi = t + s * 512;              // 2048 float4
                int row = fi >> 4, q4 = fi & 15;
                float4 v = Pf4[fi];
                *(uint2*)(smu + OFF_A1 + row * 36 + q4 * 2) =
                    make_uint2(pack_f16x2(v.x, v.y), pack_f16x2(v.z, v.w));
            }
            if (t < CH) qs[t] = g_QKV[bi * QKVW + t];
        }
        __syncthreads();       // A1/qs ready; staging P consumed

        // ---- prefetch next edge tile into P ----
        {
            int nt2 = tile + EGRID;
            if (nt2 < NT) {
                int nbi = nt2 >> 2, njt = nt2 & 3;
                const float4* src = (const float4*)(edge_attr + ((size_t)nbi * NN + njt * TJM) * EH);
#pragma unroll
                for (int s = 0; s < 4; s++) {
                    int fi = t + s * 512;
                    cp16(p_sm + fi * 16, src + fi);
                }
            }
            CP_COMMIT();
        }

        // ---- phase 1: e[128,128] = A1[128,64] x We, 4 fp16 k16-steps ----
        float acc[2][4][4];
#pragma unroll
        for (int mf = 0; mf < 2; mf++)
#pragma unroll
            for (int nf = 0; nf < 4; nf++)
#pragma unroll
                for (int i = 0; i < 4; i++) acc[mf][nf][i] = 0.f;

#pragma unroll
        for (int ks = 0; ks < 4; ks++) {
            const int kb = ks * 8;                   // u32 offset (8 u32 = 16 k)
            uint32_t a[2][4];
#pragma unroll
            for (int mf = 0; mf < 2; mf++) {
                int r0 = OFF_A1 + (m0 + mf * 16 + g) * 36 + kb + c4;
                int r1 = r0 + 8 * 36;
                a[mf][0] = smu[r0];     a[mf][1] = smu[r1];
                a[mf][2] = smu[r0 + 4]; a[mf][3] = smu[r1 + 4];
            }
#pragma unroll
            for (int nf = 0; nf < 4; nf++) {
                int bidx = OFF_B1 + (kb + c4) * 136 + n0 + nf * 8 + g;
                uint32_t b0 = smu[bidx], b1 = smu[bidx + 4 * 136];
#pragma unroll
                for (int mf = 0; mf < 2; mf++)
                    mma_f16(acc[mf][nf], a[mf][0], a[mf][1], a[mf][2], a[mf][3], b0, b1);
            }
        }

        // ---- epilogue 1: raw = (e+be)*q*k (K from smem), logits;
        //      store raw fp16x2 into A2 (disjoint from A1 -> no barrier) ----
#pragma unroll
        for (int mf = 0; mf < 2; mf++) {
#pragma unroll
            for (int cih = 0; cih < 2; cih++) {
                int r = m0 + mf * 16 + g + cih * 8;
                const float* kr = ksm + r * 136;
                float lg0 = 0.f, lg1 = 0.f;
#pragma unroll
                for (int nf = 0; nf < 4; nf++) {
                    int c = n0 + nf * 8 + 2 * c4;
                    float2 kk = *(const float2*)(kr + c);
                    float2 qq = *(const float2*)(qs + c);
                    float2 bb = *(const float2*)(bes + c);
                    float r0 = (acc[mf][nf][cih * 2 + 0] + bb.x) * qq.x * kk.x;
                    float r1 = (acc[mf][nf][cih * 2 + 1] + bb.y) * qq.y * kk.y;
                    smu[OFF_A2 + r * 68 + n0h + nf * 4 + c4] = pack_f16x2(r0, r1);
                    float p = r0 + r1;
                    if (nf < 2) lg0 += p; else lg1 += p;
                }
                lg0 += __shfl_xor_sync(0xffffffffu, lg0, 1);
                lg0 += __shfl_xor_sync(0xffffffffu, lg0, 2);
                lg1 += __shfl_xor_sync(0xffffffffu, lg1, 1);
                lg1 += __shfl_xor_sync(0xffffffffu, lg1, 2);
                if (c4 == 0) {
                    *(float2*)(g_LOG + ((size_t)bi * NN + jbase + r) * NH + 2 * (w >> 2)) =
                        make_float2(lg0 * 0.25f, lg1 * 0.25f);
                }
            }
        }
        __syncthreads();       // raw complete; K staging consumed

        // ---- prefetch next K tile (lands during phase 2) ----
        {
            int nt2 = tile + EGRID;
            if (nt2 < NT) {
                int nbi = nt2 >> 2, njt = nt2 & 3, nb = nbi >> 9;
                const float* kbase = g_QKV + ((size_t)(nb * NN + njt * TJM)) * QKVW + CH;
#pragma unroll
                for (int s = 0; s < 8; s++) {
                    int fi = t + s * 512;
                    int row = fi >> 5, cq = fi & 31;
                    cp16(k_sm + (row * 136 + cq * 4) * 4, kbase + (size_t)row * QKVW + cq * 4);
                }
            }
            CP_COMMIT();
        }

        // ---- phase 2 (transposed): out^T[64,128] = Weo^T x raw^T, 8 steps ----
        float o[4][4];
#pragma unroll
        for (int nf = 0; nf < 4; nf++)
#pragma unroll
            for (int i = 0; i < 4; i++) o[nf][i] = 0.f;

#pragma unroll
        for (int ks = 0; ks < 8; ks++) {
            const int kb = ks * 8;
#pragma unroll
            for (int nf = 0; nf < 4; nf++) {
                int bidx = OFF_A2 + (jn + nf * 8 + g) * 68 + kb + c4;
                uint32_t b0 = smu[bidx], b1 = smu[bidx + 4];
                mma_f16(o[nf], areg[ks][0], areg[ks][1], areg[ks][2], areg[ks][3], b0, b1);
            }
        }

        // ---- epilogue 2: + beo, scatter-store (out is transposed) ----
#pragma unroll
        for (int nf = 0; nf < 4; nf++) {
            int j = jn + nf * 8 + 2 * c4;
            float* d0 = edge_out + ((size_t)bi * NN + jbase + j) * EH + eo0 + g;
            float* d1 = d0 + EH;      // j+1
            d0[0] = o[nf][0] + beo0;
            d1[0] = o[nf][1] + beo0;
            d0[8] = o[nf][2] + beo1;
            d1[8] = o[nf][3] + beo1;
        }
    }
}

// ---------------------------------------------------------------------------
// Kernel C: masked softmax over j, node = att @ v, node_out = node @ Wno + bno
// ---------------------------------------------------------------------------
__global__ void __launch_bounds__(512) softmax_node_kernel(
    const int* __restrict__ mask,
    const float* __restrict__ Wno, const float* __restrict__ bno,
    float* __restrict__ node_out)
{
    __shared__ float ls[NN * 9];        // stride 9: conflict-free column walks
    __shared__ float partial[16 * 132];
    __shared__ float np[16 * 132];
    __shared__ float redm[2][NH], reds[2][NH];
    __shared__ float node_s[CH];
    __shared__ float invs[NH];
    __shared__ int msk[NN];

    int bi = blockIdx.x, b = bi >> 9, t = threadIdx.x;

    if (t < NN) msk[t] = mask[b * NN + t];
    __syncthreads();

    const float4* Lp = (const float4*)(g_LOG + (size_t)bi * NN * NH);
#pragma unroll
    for (int s = 0; s < 2; s++) {
        int fi = t + s * 512;
        float4 v = Lp[fi];
        int j = fi >> 1, hb = (fi & 1) * 4;
        if (!msk[j]) { v.x = v.y = v.z = v.w = -FLT_MAX; }
        ls[j * 9 + hb + 0] = v.x;
        ls[j * 9 + hb + 1] = v.y;
        ls[j * 9 + hb + 2] = v.z;
        ls[j * 9 + hb + 3] = v.w;
    }
    __syncthreads();

    {   // softmax: 2 warps per head (warp w: head w&7, j-half w>>3)
        int wH = (t >> 5) & 7, half = t >> 8, l = t & 31;
        int jb = half * 256 + l;
        float m = -FLT_MAX;
#pragma unroll
        for (int k = 0; k < 8; k++)
            m = fmaxf(m, ls[(jb + 32 * k) * 9 + wH]);
#pragma unroll
        for (int off = 16; off; off >>= 1)
            m = fmaxf(m, __shfl_xor_sync(0xffffffffu, m, off));
        if (l == 0) redm[half][wH] = m;
        __syncthreads();
        m = fmaxf(redm[0][wH], redm[1][wH]);
        float s = 0.f;
#pragma unroll
        for (int k = 0; k < 8; k++) {
            int j = jb + 32 * k;
            float p = __expf(ls[j * 9 + wH] - m);
            ls[j * 9 + wH] = p;
            s += p;
        }
#pragma unroll
        for (int off = 16; off; off >>= 1)
            s += __shfl_xor_sync(0xffffffffu, s, off);
        if (l == 0) reds[half][wH] = s;
        __syncthreads();
        if (t < NH) invs[t] = 1.f / (reds[0][t] + reds[1][t]);
    }

    {   // attention * V: warp wq owns 32 j-rows; lane l -> channels 4l..4l+3
        int wq = t >> 5, l = t & 31, h = l >> 2;
        const float4* Vp = (const float4*)(g_QKV + (size_t)(b * NN + wq * 32) * QKVW + 2 * CH);
        const float* lsp = ls + (wq * 32) * 9 + h;
        float4 a = make_float4(0.f, 0.f, 0.f, 0.f);
#pragma unroll 8
        for (int j = 0; j < 32; j++) {
            float p = lsp[j * 9];
            float4 v = __ldg(Vp + (size_t)j * (QKVW / 4) + l);
            a.x = fmaf(p, v.x, a.x);
            a.y = fmaf(p, v.y, a.y);
            a.z = fmaf(p, v.z, a.z);
            a.w = fmaf(p, v.w, a.w);
        }
        *(float4*)(partial + wq * 132 + 4 * l) = a;
    }
    __syncthreads();

    if (t < CH) {
        float s = 0.f;
#pragma unroll
        for (int p = 0; p < 16; p++) s += partial[p * 132 + t];
        node_s[t] = s * invs[t >> 4];
    }
    __syncthreads();

    {   // node @ Wno: warp ws owns k-slice ws*8..+8; lane -> cols 4l..4l+3
        int ws = t >> 5, l = t & 31;
        float4 o = make_float4(0.f, 0.f, 0.f, 0.f);
#pragma unroll
        for (int k = 0; k < 8; k++) {
            float s = node_s[ws * 8 + k];
            float4 wv = __ldg((const float4*)(Wno + (ws * 8 + k) * CH) + l);
            o.x = fmaf(s, wv.x, o.x);
            o.y = fmaf(s, wv.y, o.y);
            o.z = fmaf(s, wv.z, o.z);
            o.w = fmaf(s, wv.w, o.w);
        }
        *(float4*)(np + ws * 132 + 4 * l) = o;
    }
    __syncthreads();

    if (t < CH) {
        float r = bno[t];
#pragma unroll
        for (int p = 0; p < 16; p++) r += np[p * 132 + t];
        node_out[bi * CH + t] = r;
    }
}

// ---------------------------------------------------------------------------
extern "C" void kernel_launch(void* const* d_in, const int* in_sizes, int n_in,
                              void* d_out, int out_size)
{
    const float* x         = (const float*)d_in[0];
    const float* edge_attr = (const float*)d_in[1];
    const int*   mask      = (const int*)d_in[2];
    const float* Wqkv      = (const float*)d_in[3];
    const float* bqkv      = (const float*)d_in[4];
    const float* We        = (const float*)d_in[5];
    const float* be        = (const float*)d_in[6];
    const float* Wno       = (const float*)d_in[7];
    const float* bno       = (const float*)d_in[8];
    const float* Weo       = (const float*)d_in[9];
    const float* beo       = (const float*)d_in[10];

    float* out      = (float*)d_out;
    float* node_out = out;                       // (2,512,128)
    float* edge_out = out + NB * NN * CH;        // (2,512,512,64)

    prep_kernel<<<16, 256>>>(We);
    qkv_kernel<<<128, QKVW>>>(x, Wqkv, bqkv);

    size_t shmem = SMEM_U32 * sizeof(uint32_t);  // 174080 B
    cudaFuncSetAttribute(edge_mma_kernel,
                         cudaFuncAttributeMaxDynamicSharedMemorySize, (int)shmem);
    edge_mma_kernel<<<EGRID, 512, shmem>>>(edge_attr, be, beo, Weo, edge_out);

    softmax_node_kernel<<<NB * NN, 512>>>(mask, Wno, bno, node_out);
}

// round 14
// speedup vs baseline: 3.7464x; 1.0415x over previous
#include <cuda_runtime.h>
#include <cuda_fp16.h>
#include <cstdint>
#include <float.h>

#define NB 2
#define NN 512
#define NH 8
#define CH 128      // n_head * head_hidden
#define EH 64       // edge hidden
#define QKVW 384
#define TJM 64      // j-rows per tile (MMA M)
#define NT (NB * NN * (NN / TJM))   // 8192 tiles
#define EGRID 296   // 2 CTAs per SM

// Scratch (device globals)
__device__ float g_QKV[NB * NN * QKVW];              // q|k|v per node row
__device__ float g_LOG[(size_t)NB * NN * NN * NH];   // attention logits
__device__ uint32_t g_WeP[32 * 136];                 // We fp16x2 [k2=32][c=128] stride 136

// ---------------------------------------------------------------------------
// helpers
// ---------------------------------------------------------------------------
__device__ __forceinline__ uint32_t pack_f16x2(float lo, float hi) {
    uint32_t d;
    asm("cvt.rn.f16x2.f32 %0, %1, %2;" : "=r"(d) : "f"(hi), "f"(lo));
    return d;
}

__device__ __forceinline__ void mma_f16(float* c,
    uint32_t a0, uint32_t a1, uint32_t a2, uint32_t a3,
    uint32_t b0, uint32_t b1)
{
    asm volatile(
        "mma.sync.aligned.m16n8k16.row.col.f32.f16.f16.f32 "
        "{%0,%1,%2,%3}, {%4,%5,%6,%7}, {%8,%9}, {%0,%1,%2,%3};"
        : "+f"(c[0]), "+f"(c[1]), "+f"(c[2]), "+f"(c[3])
        : "r"(a0), "r"(a1), "r"(a2), "r"(a3), "r"(b0), "r"(b1));
}

__device__ __forceinline__ uint32_t smem_u32(const void* p) {
    uint32_t a;
    asm("{ .reg .u64 t; cvta.to.shared.u64 t, %1; cvt.u32.u64 %0, t; }"
        : "=r"(a) : "l"(p));
    return a;
}
__device__ __forceinline__ void cp16(uint32_t smaddr, const void* g) {
    asm volatile("cp.async.cg.shared.global [%0], [%1], 16;"
                 :: "r"(smaddr), "l"(g) : "memory");
}
#define CP_COMMIT() asm volatile("cp.async.commit_group;" ::: "memory")
#define CP_WAIT0()  asm volatile("cp.async.wait_group 0;" ::: "memory")

// SMEM map (u32 units), 96 KB total -> 2 CTAs/SM.
#define OFF_B1   0        // 4352   We fp16x2 [32][136]
#define OFF_A1   4352     // 2304   edge tile fp16x2 [64][36]
#define OFF_A2   6656     // 4352   raw fp16x2 [64][68]
#define OFF_P    11008    // 4096   fp32 edge tile staging [64][64]
#define OFF_K    15104    // 8704   K tile fp32 [64][136]
#define OFF_QS   23808    // 128 floats
#define OFF_BES  23936    // 128 floats
#define SMEM_U32 24064    // 96256 bytes

// ---------------------------------------------------------------------------
// Kernel P: We -> packed fp16x2 along k
// ---------------------------------------------------------------------------
__global__ void prep_kernel(const float* __restrict__ We) {
    int t = blockIdx.x * 256 + threadIdx.x;   // 0..4095
    if (t < 32 * 128) {
        int k2 = t >> 7, c = t & 127;
        g_WeP[k2 * 136 + c] = pack_f16x2(We[(2 * k2) * CH + c], We[(2 * k2 + 1) * CH + c]);
    }
}

// ---------------------------------------------------------------------------
// Kernel A: qkv = x @ Wqkv + bqkv.  128 blocks x 384 threads, 8 rows/block.
// ---------------------------------------------------------------------------
__global__ void __launch_bounds__(QKVW) qkv_kernel(
    const float* __restrict__ x, const float* __restrict__ W,
    const float* __restrict__ bias)
{
    __shared__ float xs[8 * CH];
    const int t = threadIdx.x;
    const int r0 = blockIdx.x * 8;

    for (int i = t; i < 8 * CH; i += QKVW) xs[i] = x[r0 * CH + i];
    float bcol = bias[t];
    __syncthreads();

    float acc[8];
#pragma unroll
    for (int r = 0; r < 8; r++) acc[r] = bcol;

#pragma unroll 4
    for (int k = 0; k < CH; k += 4) {
        float w0 = __ldg(W + (k + 0) * QKVW + t);
        float w1 = __ldg(W + (k + 1) * QKVW + t);
        float w2 = __ldg(W + (k + 2) * QKVW + t);
        float w3 = __ldg(W + (k + 3) * QKVW + t);
#pragma unroll
        for (int r = 0; r < 8; r++) {
            float4 xv = *(const float4*)(xs + r * CH + k);
            acc[r] = fmaf(xv.x, w0, acc[r]);
            acc[r] = fmaf(xv.y, w1, acc[r]);
            acc[r] = fmaf(xv.z, w2, acc[r]);
            acc[r] = fmaf(xv.w, w3, acc[r]);
        }
    }
#pragma unroll
    for (int r = 0; r < 8; r++) g_QKV[(r0 + r) * QKVW + t] = acc[r];
}

// ---------------------------------------------------------------------------
// Kernel B: persistent fused edge pipeline, fp16 mma (fp32 accum).
// TJM=64, 256 threads, 2 CTAs/SM for cross-CTA stall hiding.
// ---------------------------------------------------------------------------
__global__ void __launch_bounds__(256, 2) edge_mma_kernel(
    const float* __restrict__ edge_attr,
    const float* __restrict__ be, const float* __restrict__ beo,
    const float* __restrict__ Weo,
    float* __restrict__ edge_out)
{
    extern __shared__ uint32_t smu[];
    float* qs  = (float*)(smu + OFF_QS);
    float* bes = (float*)(smu + OFF_BES);
    float* ksm = (float*)(smu + OFF_K);
    const uint32_t sb = smem_u32(smu);
    const uint32_t p_sm = sb + OFF_P * 4;
    const uint32_t k_sm = sb + OFF_K * 4;

    const int t = threadIdx.x, lane = t & 31, w = t >> 5;   // 8 warps
    const int g = lane >> 2, c4 = lane & 3;
    // phase 1 mapping: 2m x 4n warp grid over [64j x 128c]
    const int m0 = (w & 1) * 32, n0 = (w >> 1) * 32;
    const int n0h = n0 >> 1;                    // u32 col base in A2
    const int wn = w >> 1;                      // head-pair group
    // phase 2 mapping: 4(eo) x 2(j) warp grid over [64eo x 64j]
    const int eo0 = (w & 3) * 16, jn = (w >> 2) * 32;

    // ---- one-time: We tile to smem, bias, persistent Weo^T fp16 fragments ----
    for (int i = t; i < 32 * 136; i += 256) smu[OFF_B1 + i] = g_WeP[i];
    if (t < CH) bes[t] = be[t];

    const float beo0 = beo[eo0 + g], beo1 = beo[eo0 + g + 8];

    uint32_t areg[8][4];                        // Weo^T [64eo][128k] fragments
#pragma unroll
    for (int ks = 0; ks < 8; ks++) {
        int k2a = ks * 8 + c4;                  // packed-k index (pairs)
        int k2b = k2a + 4;
        areg[ks][0] = pack_f16x2(__ldg(Weo + (2 * k2a)     * EH + eo0 + g),
                                 __ldg(Weo + (2 * k2a + 1) * EH + eo0 + g));
        areg[ks][1] = pack_f16x2(__ldg(Weo + (2 * k2a)     * EH + eo0 + g + 8),
                                 __ldg(Weo + (2 * k2a + 1) * EH + eo0 + g + 8));
        areg[ks][2] = pack_f16x2(__ldg(Weo + (2 * k2b)     * EH + eo0 + g),
                                 __ldg(Weo + (2 * k2b + 1) * EH + eo0 + g));
        areg[ks][3] = pack_f16x2(__ldg(Weo + (2 * k2b)     * EH + eo0 + g + 8),
                                 __ldg(Weo + (2 * k2b + 1) * EH + eo0 + g + 8));
    }

    // ---- prefetch first tile: edge + K ----
    int tile = blockIdx.x;
    if (tile < NT) {
        int bi = tile >> 3, jt = tile & 7, b0v = bi >> 9;
        const float4* src = (const float4*)(edge_attr + ((size_t)bi * NN + jt * TJM) * EH);
#pragma unroll
        for (int s = 0; s < 4; s++) {            // 1024 float4
            int fi = t + s * 256;
            cp16(p_sm + fi * 16, src + fi);
        }
        const float* kbase = g_QKV + ((size_t)(b0v * NN + jt * TJM)) * QKVW + CH;
#pragma unroll
        for (int s = 0; s < 8; s++) {            // 2048 float4
            int fi = t + s * 256;
            int row = fi >> 5, cq = fi & 31;
            cp16(k_sm + (row * 136 + cq * 4) * 4, kbase + (size_t)row * QKVW + cq * 4);
        }
    }
    CP_COMMIT();

    for (; tile < NT; tile += EGRID) {
        const int bi = tile >> 3, jt = tile & 7;
        const int jbase = jt * TJM;

        CP_WAIT0();
        __syncthreads();       // staging P + K valid; prior tile done

        // ---- staged fp32 tile -> A1 fp16x2 [64][36]; q row ----
        {
            const float4* Pf4 = (const float4*)(smu + OFF_P);
#pragma unroll
            for (int s = 0; s < 4; s++) {
                int fi = t + s * 256;              // 1024 float4
                int row = fi >> 4, q4 = fi & 15;
                float4 v = Pf4[fi];
                *(uint2*)(smu + OFF_A1 + row * 36 + q4 * 2) =
                    make_uint2(pack_f16x2(v.x, v.y), pack_f16x2(v.z, v.w));
            }
            if (t < CH) qs[t] = g_QKV[bi * QKVW + t];
        }
        __syncthreads();       // A1/qs ready; staging P consumed

        // ---- prefetch next edge tile into P ----
        {
            int nt2 = tile + EGRID;
            if (nt2 < NT) {
                int nbi = nt2 >> 3, njt = nt2 & 7;
                const float4* src = (const float4*)(edge_attr + ((size_t)nbi * NN + njt * TJM) * EH);
#pragma unroll
                for (int s = 0; s < 4; s++) {
                    int fi = t + s * 256;
                    cp16(p_sm + fi * 16, src + fi);
                }
            }
            CP_COMMIT();
        }

        // ---- phase 1: e[64,128] = A1[64,64] x We, 4 fp16 k16-steps ----
        float acc[2][4][4];
#pragma unroll
        for (int mf = 0; mf < 2; mf++)
#pragma unroll
            for (int nf = 0; nf < 4; nf++)
#pragma unroll
                for (int i = 0; i < 4; i++) acc[mf][nf][i] = 0.f;

#pragma unroll
        for (int ks = 0; ks < 4; ks++) {
            const int kb = ks * 8;                   // u32 offset (8 u32 = 16 k)
            uint32_t a[2][4];
#pragma unroll
            for (int mf = 0; mf < 2; mf++) {
                int r0 = OFF_A1 + (m0 + mf * 16 + g) * 36 + kb + c4;
                int r1 = r0 + 8 * 36;
                a[mf][0] = smu[r0];     a[mf][1] = smu[r1];
                a[mf][2] = smu[r0 + 4]; a[mf][3] = smu[r1 + 4];
            }
#pragma unroll
            for (int nf = 0; nf < 4; nf++) {
                int bidx = OFF_B1 + (kb + c4) * 136 + n0 + nf * 8 + g;
                uint32_t b0 = smu[bidx], b1 = smu[bidx + 4 * 136];
#pragma unroll
                for (int mf = 0; mf < 2; mf++)
                    mma_f16(acc[mf][nf], a[mf][0], a[mf][1], a[mf][2], a[mf][3], b0, b1);
            }
        }

        // ---- epilogue 1: raw = (e+be)*q*k (K from smem), logits;
        //      store raw fp16x2 into A2 ----
#pragma unroll
        for (int mf = 0; mf < 2; mf++) {
#pragma unroll
            for (int cih = 0; cih < 2; cih++) {
                int r = m0 + mf * 16 + g + cih * 8;
                const float* kr = ksm + r * 136;
                float lg0 = 0.f, lg1 = 0.f;
#pragma unroll
                for (int nf = 0; nf < 4; nf++) {
                    int c = n0 + nf * 8 + 2 * c4;
                    float2 kk = *(const float2*)(kr + c);
                    float2 qq = *(const float2*)(qs + c);
                    float2 bb = *(const float2*)(bes + c);
                    float r0 = (acc[mf][nf][cih * 2 + 0] + bb.x) * qq.x * kk.x;
                    float r1 = (acc[mf][nf][cih * 2 + 1] + bb.y) * qq.y * kk.y;
                    smu[OFF_A2 + r * 68 + n0h + nf * 4 + c4] = pack_f16x2(r0, r1);
                    float p = r0 + r1;
                    if (nf < 2) lg0 += p; else lg1 += p;
                }
                lg0 += __shfl_xor_sync(0xffffffffu, lg0, 1);
                lg0 += __shfl_xor_sync(0xffffffffu, lg0, 2);
                lg1 += __shfl_xor_sync(0xffffffffu, lg1, 1);
                lg1 += __shfl_xor_sync(0xffffffffu, lg1, 2);
                if (c4 == 0) {
                    *(float2*)(g_LOG + ((size_t)bi * NN + jbase + r) * NH + 2 * wn) =
                        make_float2(lg0 * 0.25f, lg1 * 0.25f);
                }
            }
        }
        __syncthreads();       // raw complete; K staging consumed

        // ---- prefetch next K tile (lands during phase 2) ----
        {
            int nt2 = tile + EGRID;
            if (nt2 < NT) {
                int nbi = nt2 >> 3, njt = nt2 & 7, nb = nbi >> 9;
                const float* kbase = g_QKV + ((size_t)(nb * NN + njt * TJM)) * QKVW + CH;
#pragma unroll
                for (int s = 0; s < 8; s++) {
                    int fi = t + s * 256;
                    int row = fi >> 5, cq = fi & 31;
                    cp16(k_sm + (row * 136 + cq * 4) * 4, kbase + (size_t)row * QKVW + cq * 4);
                }
            }
            CP_COMMIT();
        }

        // ---- phase 2 (transposed): out^T[64,64] = Weo^T x raw^T, 8 steps ----
        float o[4][4];
#pragma unroll
        for (int nf = 0; nf < 4; nf++)
#pragma unroll
            for (int i = 0; i < 4; i++) o[nf][i] = 0.f;

#pragma unroll
        for (int ks = 0; ks < 8; ks++) {
            const int kb = ks * 8;
#pragma unroll
            for (int nf = 0; nf < 4; nf++) {
                int bidx = OFF_A2 + (jn + nf * 8 + g) * 68 + kb + c4;
                uint32_t b0 = smu[bidx], b1 = smu[bidx + 4];
                mma_f16(o[nf], areg[ks][0], areg[ks][1], areg[ks][2], areg[ks][3], b0, b1);
            }
        }

        // ---- epilogue 2: + beo, scatter-store (out is transposed) ----
#pragma unroll
        for (int nf = 0; nf < 4; nf++) {
            int j = jn + nf * 8 + 2 * c4;
            float* d0 = edge_out + ((size_t)bi * NN + jbase + j) * EH + eo0 + g;
            float* d1 = d0 + EH;      // j+1
            d0[0] = o[nf][0] + beo0;
            d1[0] = o[nf][1] + beo0;
            d0[8] = o[nf][2] + beo1;
            d1[8] = o[nf][3] + beo1;
        }
    }
}

// ---------------------------------------------------------------------------
// Kernel C: masked softmax over j, node = att @ v, node_out = node @ Wno + bno
// ---------------------------------------------------------------------------
__global__ void __launch_bounds__(512) softmax_node_kernel(
    const int* __restrict__ mask,
    const float* __restrict__ Wno, const float* __restrict__ bno,
    float* __restrict__ node_out)
{
    __shared__ float ls[NN * 9];        // stride 9: conflict-free column walks
    __shared__ float partial[16 * 132];
    __shared__ float np[16 * 132];
    __shared__ float redm[2][NH], reds[2][NH];
    __shared__ float node_s[CH];
    __shared__ float invs[NH];
    __shared__ int msk[NN];

    int bi = blockIdx.x, b = bi >> 9, t = threadIdx.x;

    if (t < NN) msk[t] = mask[b * NN + t];
    __syncthreads();

    const float4* Lp = (const float4*)(g_LOG + (size_t)bi * NN * NH);
#pragma unroll
    for (int s = 0; s < 2; s++) {
        int fi = t + s * 512;
        float4 v = Lp[fi];
        int j = fi >> 1, hb = (fi & 1) * 4;
        if (!msk[j]) { v.x = v.y = v.z = v.w = -FLT_MAX; }
        ls[j * 9 + hb + 0] = v.x;
        ls[j * 9 + hb + 1] = v.y;
        ls[j * 9 + hb + 2] = v.z;
        ls[j * 9 + hb + 3] = v.w;
    }
    __syncthreads();

    {   // softmax: 2 warps per head (warp w: head w&7, j-half w>>3)
        int wH = (t >> 5) & 7, half = t >> 8, l = t & 31;
        int jb = half * 256 + l;
        float m = -FLT_MAX;
#pragma unroll
        for (int k = 0; k < 8; k++)
            m = fmaxf(m, ls[(jb + 32 * k) * 9 + wH]);
#pragma unroll
        for (int off = 16; off; off >>= 1)
            m = fmaxf(m, __shfl_xor_sync(0xffffffffu, m, off));
        if (l == 0) redm[half][wH] = m;
        __syncthreads();
        m = fmaxf(redm[0][wH], redm[1][wH]);
        float s = 0.f;
#pragma unroll
        for (int k = 0; k < 8; k++) {
            int j = jb + 32 * k;
            float p = __expf(ls[j * 9 + wH] - m);
            ls[j * 9 + wH] = p;
            s += p;
        }
#pragma unroll
        for (int off = 16; off; off >>= 1)
            s += __shfl_xor_sync(0xffffffffu, s, off);
        if (l == 0) reds[half][wH] = s;
        __syncthreads();
        if (t < NH) invs[t] = 1.f / (reds[0][t] + reds[1][t]);
    }

    {   // attention * V: warp wq owns 32 j-rows; lane l -> channels 4l..4l+3
        int wq = t >> 5, l = t & 31, h = l >> 2;
        const float4* Vp = (const float4*)(g_QKV + (size_t)(b * NN + wq * 32) * QKVW + 2 * CH);
        const float* lsp = ls + (wq * 32) * 9 + h;
        float4 a = make_float4(0.f, 0.f, 0.f, 0.f);
#pragma unroll 8
        for (int j = 0; j < 32; j++) {
            float p = lsp[j * 9];
            float4 v = __ldg(Vp + (size_t)j * (QKVW / 4) + l);
            a.x = fmaf(p, v.x, a.x);
            a.y = fmaf(p, v.y, a.y);
            a.z = fmaf(p, v.z, a.z);
            a.w = fmaf(p, v.w, a.w);
        }
        *(float4*)(partial + wq * 132 + 4 * l) = a;
    }
    __syncthreads();

    if (t < CH) {
        float s = 0.f;
#pragma unroll
        for (int p = 0; p < 16; p++) s += partial[p * 132 + t];
        node_s[t] = s * invs[t >> 4];
    }
    __syncthreads();

    {   // node @ Wno: warp ws owns k-slice ws*8..+8; lane -> cols 4l..4l+3
        int ws = t >> 5, l = t & 31;
        float4 o = make_float4(0.f, 0.f, 0.f, 0.f);
#pragma unroll
        for (int k = 0; k < 8; k++) {
            float s = node_s[ws * 8 + k];
            float4 wv = __ldg((const float4*)(Wno + (ws * 8 + k) * CH) + l);
            o.x = fmaf(s, wv.x, o.x);
            o.y = fmaf(s, wv.y, o.y);
            o.z = fmaf(s, wv.z, o.z);
            o.w = fmaf(s, wv.w, o.w);
        }
        *(float4*)(np + ws * 132 + 4 * l) = o;
    }
    __syncthreads();

    if (t < CH) {
        float r = bno[t];
#pragma unroll
        for (int p = 0; p < 16; p++) r += np[p * 132 + t];
        node_out[bi * CH + t] = r;
    }
}

// ---------------------------------------------------------------------------
extern "C" void kernel_launch(void* const* d_in, const int* in_sizes, int n_in,
                              void* d_out, int out_size)
{
    const float* x         = (const float*)d_in[0];
    const float* edge_attr = (const float*)d_in[1];
    const int*   mask      = (const int*)d_in[2];
    const float* Wqkv      = (const float*)d_in[3];
    const float* bqkv      = (const float*)d_in[4];
    const float* We        = (const float*)d_in[5];
    const float* be        = (const float*)d_in[6];
    const float* Wno       = (const float*)d_in[7];
    const float* bno       = (const float*)d_in[8];
    const float* Weo       = (const float*)d_in[9];
    const float* beo       = (const float*)d_in[10];

    float* out      = (float*)d_out;
    float* node_out = out;                       // (2,512,128)
    float* edge_out = out + NB * NN * CH;        // (2,512,512,64)

    prep_kernel<<<16, 256>>>(We);
    qkv_kernel<<<128, QKVW>>>(x, Wqkv, bqkv);

    size_t shmem = SMEM_U32 * sizeof(uint32_t);  // 96256 B
    cudaFuncSetAttribute(edge_mma_kernel,
                         cudaFuncAttributeMaxDynamicSharedMemorySize, (int)shmem);
    edge_mma_kernel<<<EGRID, 256, shmem>>>(edge_attr, be, beo, Weo, edge_out);

    softmax_node_kernel<<<NB * NN, 512>>>(mask, Wno, bno, node_out);
}